// round 14
// baseline (speedup 1.0000x reference)
#include <cuda_runtime.h>
#include <cuda_fp16.h>
#include <cstdint>
#include <math.h>

// ---------------- config ----------------
#define BATCH   16
#define SEQ     2048
#define NCH     64
#define DMODEL  256
#define DINNER  512
#define DSTATE  64
#define NHEADS  8
#define HP      64
#define CONVDIM 640          // DINNER + 2*DSTATE
#define DPROJ   1160         // 2*DINNER + 2*DSTATE + NHEADS
#define NROWS   (BATCH*SEQ)  // 32768
#define NLAYERS 4
#define LN_EPS  1e-5f
#define DPROJP  1280         // DPROJ padded to 128
#define TCH     32           // conv time-chunk

// ---------------- scratch (device globals; allocation-free) ----------------
__device__ float  g_h[NROWS*DMODEL];        // residual stream (fp32)
__device__ __half g_hh[NROWS*DMODEL];       // fp16 copy of h
__device__ __half g_zxh[NROWS*DPROJ];       // zxbcdt (fp16)
__device__ __half g_xacth[NROWS*DINNER];    // silu(conv(x)) (fp16, x part only)
__device__ float  g_bcf[NROWS*2*DSTATE];    // conv'd B,C (fp32)
__device__ float2 g_dtA[NROWS*NHEADS];      // (softplus dt, exp(dt*A)) fp32
__device__ __half g_yq[4][NROWS*DINNER];    // scan partials (n quarters)
__device__ __half g_mh[NROWS*DMODEL];       // y @ W_out (fp16)

// fp16 activations (GEMM A operands)
__device__ __half g_xh[NROWS*NCH];
__device__ __half g_yh[NROWS*DINNER];

// fp16 transposed weights (GEMM B operands), [Npad][K]
__device__ __half g_linw[DMODEL*NCH];
__device__ __half g_winw[NLAYERS*DPROJP*DMODEL];
__device__ __half g_woutw[NLAYERS*DMODEL*DINNER];

__device__ __forceinline__ float siluf(float x) {
    return x * (1.f / (1.f + __expf(-x)));
}

__device__ __forceinline__ uint32_t smem_u32(const void* p) {
    uint32_t a;
    asm("{ .reg .u64 t; cvta.to.shared.u64 t, %1; cvt.u32.u64 %0, t; }"
        : "=r"(a) : "l"(p));
    return a;
}

#define LDM_X4(r0, r1, r2, r3, addr) \
    asm volatile("ldmatrix.sync.aligned.m8n8.x4.shared.b16 {%0,%1,%2,%3}, [%4];" \
        : "=r"(r0), "=r"(r1), "=r"(r2), "=r"(r3) : "r"(addr))

#define MMA_FP16(c, a, b0v, b1v) \
    asm volatile("mma.sync.aligned.m16n8k16.row.col.f32.f16.f16.f32 " \
        "{%0,%1,%2,%3}, {%4,%5,%6,%7}, {%8,%9}, {%0,%1,%2,%3};" \
        : "+f"((c)[0]), "+f"((c)[1]), "+f"((c)[2]), "+f"((c)[3]) \
        : "r"((a)[0]), "r"((a)[1]), "r"((a)[2]), "r"((a)[3]), \
          "r"(b0v), "r"(b1v))

#define CP16(dst, src) \
    asm volatile("cp.async.cg.shared.global [%0], [%1], 16;" \
        :: "r"(dst), "l"(src) : "memory")
#define CPCOMMIT() asm volatile("cp.async.commit_group;" ::: "memory")
#define CPWAIT(n)  asm volatile("cp.async.wait_group %0;" :: "n"(n) : "memory")

// ---------------- weight / input conversion ----------------
__global__ void k_cvt_w(const float* __restrict__ src, __half* __restrict__ dh,
                        int K, int N, int srcStrideLayer, int dstStrideLayer)
{
    int n = blockIdx.x;
    int l = blockIdx.y;
    int k = threadIdx.x;                 // blockDim.x == K
    float v = (n < N) ? src[(size_t)l*srcStrideLayer + (size_t)k*N + n] : 0.f;
    dh[(size_t)l*dstStrideLayer + (size_t)n*K + k] = __float2half_rn(v);
}

__global__ void k_cvt_x(const float* __restrict__ src, __half* __restrict__ d)
{
    int i = blockIdx.x * 256 + threadIdx.x;
    d[i] = __float2half_rn(src[i]);
}

// ============================================================================
// Single-pass fp16 tensor-core GEMM (round-9 proven 2-stage version)
// ============================================================================
#define GSTRIDE 40
#define TILEB   (128*GSTRIDE*2)
#define STAGEB  (2*TILEB)
#define GT_SMEM (2*STAGEB)

__global__ __launch_bounds__(256, 2) void k_gemm_fp16(
    const __half* __restrict__ A, const __half* __restrict__ B,
    const float* __restrict__ bias, float* __restrict__ C,
    __half* __restrict__ Ch, int N, int K)
{
    extern __shared__ __align__(128) uint8_t dsm[];
    const uint32_t smb = smem_u32(dsm);

    int tid = threadIdx.x;
    int wid = tid >> 5, lane = tid & 31;
    int m0 = blockIdx.y * 128, n0 = blockIdx.x * 128;
    int wm = wid & 3, wn = wid >> 2;

    float acc[2][8][4];
#pragma unroll
    for (int mt = 0; mt < 2; mt++)
#pragma unroll
        for (int nt = 0; nt < 8; nt++)
#pragma unroll
            for (int j = 0; j < 4; j++) acc[mt][nt][j] = 0.f;

    const __half* srcs[2] = { A + (size_t)m0 * K, B + (size_t)n0 * K };
    const int row0 = tid >> 2, part = tid & 3;

    const uint32_t aoff = (uint32_t)((wm*32 + (lane & 7) + ((lane >> 3) & 1) * 8) * (GSTRIDE*2))
                        + ((lane >> 4) & 1) * 16;
    const uint32_t boff = (uint32_t)((wn*64 + (lane & 7) + ((lane >> 4) & 1) * 8) * (GSTRIDE*2))
                        + ((lane >> 3) & 1) * 16;

    const int NC = K >> 5;

#pragma unroll
    for (int t = 0; t < 2; t++) {
#pragma unroll
        for (int it = 0; it < 2; it++) {
            int r = row0 + it * 64;
            uint32_t d = smb + t * TILEB + (uint32_t)(r * (GSTRIDE*2) + part * 16);
            CP16(d, srcs[t] + (size_t)r * K + part * 8);
        }
    }
    CPCOMMIT();

    for (int c = 0; c < NC; c++) {
        int s = c & 1;
        if (c + 1 < NC) {
            uint32_t sb2 = smb + ((c + 1) & 1) * STAGEB;
            int kb = (c + 1) * 32;
#pragma unroll
            for (int t = 0; t < 2; t++) {
#pragma unroll
                for (int it = 0; it < 2; it++) {
                    int r = row0 + it * 64;
                    uint32_t d = sb2 + t * TILEB + (uint32_t)(r * (GSTRIDE*2) + part * 16);
                    CP16(d, srcs[t] + (size_t)r * K + kb + part * 8);
                }
            }
            CPCOMMIT();
            CPWAIT(1);
        } else {
            CPWAIT(0);
        }
        __syncthreads();

        uint32_t sbase = smb + s * STAGEB;
#pragma unroll
        for (int ks = 0; ks < 2; ks++) {
            uint32_t abase = sbase + aoff + ks * 32;
            uint32_t ra[2][4];
            LDM_X4(ra[0][0], ra[0][1], ra[0][2], ra[0][3], abase);
            LDM_X4(ra[1][0], ra[1][1], ra[1][2], ra[1][3],
                   abase + 16 * (GSTRIDE*2));
            uint32_t rb[8][2];
            uint32_t bbase = sbase + TILEB + boff + ks * 32;
#pragma unroll
            for (int g = 0; g < 4; g++)
                LDM_X4(rb[2*g][0], rb[2*g][1], rb[2*g+1][0], rb[2*g+1][1],
                       bbase + g * 16 * (GSTRIDE*2));
#pragma unroll
            for (int mt = 0; mt < 2; mt++)
#pragma unroll
                for (int nt = 0; nt < 8; nt++)
                    MMA_FP16(acc[mt][nt], ra[mt], rb[nt][0], rb[nt][1]);
        }
        __syncthreads();
    }

    const int gid = lane >> 2, tig = lane & 3;
#pragma unroll
    for (int mt = 0; mt < 2; mt++) {
#pragma unroll
        for (int nt = 0; nt < 8; nt++) {
            int col = n0 + wn * 64 + nt * 8 + tig * 2;
            if (col < N) {
                int r0 = m0 + wm * 32 + mt * 16 + gid;
                float2 v0 = make_float2(acc[mt][nt][0], acc[mt][nt][1]);
                float2 v1 = make_float2(acc[mt][nt][2], acc[mt][nt][3]);
                if (bias) {
                    float b0 = bias[col], b1 = bias[col + 1];
                    v0.x += b0; v0.y += b1; v1.x += b0; v1.y += b1;
                }
                if (C) {
                    *(float2*)(C + (size_t)r0 * N + col) = v0;
                    *(float2*)(C + (size_t)(r0 + 8) * N + col) = v1;
                }
                if (Ch) {
                    *(__half2*)(Ch + (size_t)r0 * N + col) =
                        __floats2half2_rn(v0.x, v0.y);
                    *(__half2*)(Ch + (size_t)(r0 + 8) * N + col) =
                        __floats2half2_rn(v1.x, v1.y);
                }
            }
        }
    }
}

// ------------- causal depthwise conv(4) + SiLU + dt/dA, t-chunked -------------
__global__ __launch_bounds__(CONVDIM) void k_conv_dt(
    const float* __restrict__ conv_w, const float* __restrict__ conv_b,
    const float* __restrict__ dt_bias, const float* __restrict__ A_log,
    int layer)
{
    int t0 = blockIdx.x * TCH;
    int b  = blockIdx.y;
    int c  = threadIdx.x;                  // 0..639

    const float* wr = conv_w + (size_t)layer*CONVDIM*4 + c*4;
    float w0 = wr[0], w1 = wr[1], w2 = wr[2], w3 = wr[3];
    float cb = conv_b[layer*CONVDIM + c];

    const __half* zc = g_zxh + (size_t)(b*SEQ)*DPROJ + DINNER + c;
    float h3 = 0.f, h2 = 0.f, h1 = 0.f;
    if (t0 >= 3) {
        h3 = __half2float(zc[(size_t)(t0-3)*DPROJ]);
        h2 = __half2float(zc[(size_t)(t0-2)*DPROJ]);
        h1 = __half2float(zc[(size_t)(t0-1)*DPROJ]);
    }

    float dtb = 0.f, Aneg = 0.f;
    const __half* dz = nullptr;
    if (c < NHEADS) {
        dtb  = dt_bias[layer*NHEADS + c];
        Aneg = -expf(A_log[layer*NHEADS + c]);
        dz   = g_zxh + (size_t)(b*SEQ)*DPROJ + DINNER + CONVDIM + c;
    }

    bool isx = (c < DINNER);
    __half* xo = g_xacth + (size_t)(b*SEQ + t0)*DINNER + c;
    float*  bo = g_bcf   + (size_t)(b*SEQ + t0)*(2*DSTATE) + (c - DINNER);

#pragma unroll 4
    for (int u = 0; u < TCH; u++) {
        float cur = __half2float(zc[(size_t)(t0+u)*DPROJ]);
        float s = cb + h3*w0 + h2*w1 + h1*w2 + cur*w3;
        float act = siluf(s);
        if (isx) xo[(size_t)u*DINNER] = __float2half_rn(act);
        else     bo[(size_t)u*(2*DSTATE)] = act;
        h3 = h2; h2 = h1; h1 = cur;
        if (c < NHEADS) {
            float draw = __half2float(dz[(size_t)(t0+u)*DPROJ]) + dtb;
            float dtv = (draw > 20.f) ? draw : log1pf(expf(draw));
            g_dtA[(size_t)(b*SEQ + t0 + u)*NHEADS + c] =
                make_float2(dtv, expf(dtv * Aneg));
        }
    }
}

// ---------------- sequential selective scan, quarter-split ----------------
// grid = 512 (bh * 4 quarters), block 256: p = tid>>2, q = tid&3,
// n-slice = quarter*16 + q*4 (4 fp32 states/thread). 4-deep register prefetch.
// Partials -> g_yq[quarter] (fp16); D-skip added by quarter 0 only.
__global__ __launch_bounds__(256) void k_scan(
    const float* __restrict__ Dp, int layer)
{
    int bh = blockIdx.x >> 2, quarter = blockIdx.x & 3;
    int b = bh >> 3, h = bh & 7;
    int tid = threadIdx.x;
    int p = tid >> 2, q = tid & 3;
    int n0 = quarter*16 + q*4;

    float S[4];
#pragma unroll
    for (int j = 0; j < 4; j++) S[j] = 0.f;

    float Dh = (quarter == 0) ? Dp[layer*NHEADS + h] : 0.f;

    const __half*  xrow = g_xacth + (size_t)(b*SEQ)*DINNER + h*HP + p;
    const float2*  dap  = g_dtA   + (size_t)(b*SEQ)*NHEADS + h;
    const float*   bcb  = g_bcf   + (size_t)(b*SEQ)*(2*DSTATE);
    __half* yp = g_yq[quarter] + (size_t)(b*SEQ)*DINNER + h*HP + p;

    float sx[4]; float2 sda[4];
    float sB[4][4], sC[4][4];
#pragma unroll
    for (int u = 0; u < 4; u++) {
        sx[u]  = __half2float(xrow[(size_t)u*DINNER]);
        sda[u] = dap[u*NHEADS];
        const float* bc = bcb + (size_t)u*(2*DSTATE);
        *(float4*)sB[u] = *(const float4*)(bc + n0);
        *(float4*)sC[u] = *(const float4*)(bc + DSTATE + n0);
    }

    for (int t = 0; t < SEQ; t += 4) {
#pragma unroll
        for (int u = 0; u < 4; u++) {
            float xv = sx[u];
            float2 da = sda[u];
            float coef = da.x * xv;
            float a0 = 0.f, a1 = 0.f;
#pragma unroll
            for (int j = 0; j < 2; j++) {
                S[j] = S[j]*da.y + coef*sB[u][j];
                a0 += S[j]*sC[u][j];
            }
#pragma unroll
            for (int j = 2; j < 4; j++) {
                S[j] = S[j]*da.y + coef*sB[u][j];
                a1 += S[j]*sC[u][j];
            }
            float acc = a0 + a1;
            acc += __shfl_xor_sync(0xffffffffu, acc, 1);
            acc += __shfl_xor_sync(0xffffffffu, acc, 2);
            if (q == 0)
                yp[(size_t)(t+u)*DINNER] = __float2half_rn(acc + Dh*xv);

            int tt = t + u + 4; if (tt > SEQ - 1) tt = SEQ - 1;
            sx[u]  = __half2float(xrow[(size_t)tt*DINNER]);
            sda[u] = dap[tt*NHEADS];
            const float* bc = bcb + (size_t)tt*(2*DSTATE);
            *(float4*)sB[u] = *(const float4*)(bc + n0);
            *(float4*)sC[u] = *(const float4*)(bc + DSTATE + n0);
        }
    }
}

// ------------- gated RMSNorm: y = rmsnorm((Σ yq) * silu(z)) -> fp16 -------------
__global__ __launch_bounds__(256) void k_gate_rms(
    const float* __restrict__ norm_w, int layer)
{
    int row = blockIdx.x;
    int tid = threadIdx.x;
    int lane = tid & 31, wid = tid >> 5;
    __shared__ float red[8];

    const __half* zrow = g_zxh + (size_t)row*DPROJ;
    size_t base = (size_t)row*DINNER;

    float y0a = __half2float(g_yq[0][base + tid])
              + __half2float(g_yq[1][base + tid])
              + __half2float(g_yq[2][base + tid])
              + __half2float(g_yq[3][base + tid]);
    float y1a = __half2float(g_yq[0][base + tid + 256])
              + __half2float(g_yq[1][base + tid + 256])
              + __half2float(g_yq[2][base + tid + 256])
              + __half2float(g_yq[3][base + tid + 256]);
    float v0 = y0a * siluf(__half2float(zrow[tid]));
    float v1 = y1a * siluf(__half2float(zrow[tid + 256]));
    float s = v0*v0 + v1*v1;
#pragma unroll
    for (int o = 16; o > 0; o >>= 1) s += __shfl_xor_sync(0xffffffffu, s, o);
    if (lane == 0) red[wid] = s;
    __syncthreads();
    if (tid < 32) {
        float v = (lane < 8) ? red[lane] : 0.f;
#pragma unroll
        for (int o = 4; o > 0; o >>= 1) v += __shfl_xor_sync(0xffffffffu, v, o);
        if (lane == 0) red[0] = v;
    }
    __syncthreads();
    float scale = rsqrtf(red[0] * (1.f/DINNER) + LN_EPS);
    g_yh[base + tid]       = __float2half_rn(v0 * scale * norm_w[layer*DINNER + tid]);
    g_yh[base + tid + 256] = __float2half_rn(v1 * scale * norm_w[layer*DINNER + tid + 256]);
}

// ---------------- residual + LayerNorm: h = LN(m + h) -> fp32 + fp16 ----------------
__global__ __launch_bounds__(256) void k_res_ln(
    const float* __restrict__ ln_w, const float* __restrict__ ln_b, int layer)
{
    int row = blockIdx.x;
    int tid = threadIdx.x;
    int lane = tid & 31, wid = tid >> 5;
    __shared__ float red1[8], red2[8];

    size_t o = (size_t)row*DMODEL + tid;
    float u = __half2float(g_mh[o]) + g_h[o];
    float s1 = u, s2 = u*u;
#pragma unroll
    for (int ofs = 16; ofs > 0; ofs >>= 1) {
        s1 += __shfl_xor_sync(0xffffffffu, s1, ofs);
        s2 += __shfl_xor_sync(0xffffffffu, s2, ofs);
    }
    if (lane == 0) { red1[wid] = s1; red2[wid] = s2; }
    __syncthreads();
    if (tid < 32) {
        float a = (lane < 8) ? red1[lane] : 0.f;
        float c = (lane < 8) ? red2[lane] : 0.f;
#pragma unroll
        for (int ofs = 4; ofs > 0; ofs >>= 1) {
            a += __shfl_xor_sync(0xffffffffu, a, ofs);
            c += __shfl_xor_sync(0xffffffffu, c, ofs);
        }
        if (lane == 0) { red1[0] = a; red2[0] = c; }
    }
    __syncthreads();
    float mu  = red1[0] * (1.f/DMODEL);
    float var = red2[0] * (1.f/DMODEL) - mu*mu;
    float outv = (u - mu) * rsqrtf(var + LN_EPS) * ln_w[layer*DMODEL + tid]
               + ln_b[layer*DMODEL + tid];
    g_h[o]  = outv;
    g_hh[o] = __float2half_rn(outv);
}

// ---- final layer: residual + LayerNorm + linear_out fused -> d_out ----
__global__ __launch_bounds__(256) void k_res_ln_out(
    const float* __restrict__ ln_w, const float* __restrict__ ln_b, int layer,
    const float* __restrict__ w, const float* __restrict__ bias,
    float* __restrict__ out)
{
    int row = blockIdx.x;
    int tid = threadIdx.x;
    int lane = tid & 31, wid = tid >> 5;
    __shared__ float red1[8], red2[8];
    __shared__ float red5[8][5];

    size_t o = (size_t)row*DMODEL + tid;
    float u = __half2float(g_mh[o]) + g_h[o];
    float s1 = u, s2 = u*u;
#pragma unroll
    for (int ofs = 16; ofs > 0; ofs >>= 1) {
        s1 += __shfl_xor_sync(0xffffffffu, s1, ofs);
        s2 += __shfl_xor_sync(0xffffffffu, s2, ofs);
    }
    if (lane == 0) { red1[wid] = s1; red2[wid] = s2; }
    __syncthreads();
    if (tid < 32) {
        float a = (lane < 8) ? red1[lane] : 0.f;
        float c = (lane < 8) ? red2[lane] : 0.f;
#pragma unroll
        for (int ofs = 4; ofs > 0; ofs >>= 1) {
            a += __shfl_xor_sync(0xffffffffu, a, ofs);
            c += __shfl_xor_sync(0xffffffffu, c, ofs);
        }
        if (lane == 0) { red1[0] = a; red2[0] = c; }
    }
    __syncthreads();
    float mu  = red1[0] * (1.f/DMODEL);
    float var = red2[0] * (1.f/DMODEL) - mu*mu;
    float outv = (u - mu) * rsqrtf(var + LN_EPS) * ln_w[layer*DMODEL + tid]
               + ln_b[layer*DMODEL + tid];

    float a0 = outv * w[tid*5 + 0];
    float a1 = outv * w[tid*5 + 1];
    float a2 = outv * w[tid*5 + 2];
    float a3 = outv * w[tid*5 + 3];
    float a4 = outv * w[tid*5 + 4];
#pragma unroll
    for (int ofs = 16; ofs > 0; ofs >>= 1) {
        a0 += __shfl_xor_sync(0xffffffffu, a0, ofs);
        a1 += __shfl_xor_sync(0xffffffffu, a1, ofs);
        a2 += __shfl_xor_sync(0xffffffffu, a2, ofs);
        a3 += __shfl_xor_sync(0xffffffffu, a3, ofs);
        a4 += __shfl_xor_sync(0xffffffffu, a4, ofs);
    }
    if (lane == 0) {
        red5[wid][0] = a0; red5[wid][1] = a1; red5[wid][2] = a2;
        red5[wid][3] = a3; red5[wid][4] = a4;
    }
    __syncthreads();
    if (tid < 5) {
        float s = 0.f;
#pragma unroll
        for (int j = 0; j < 8; j++) s += red5[j][tid];
        out[(size_t)row*5 + tid] = s + bias[tid];
    }
}

// ---------------- launcher ----------------
extern "C" void kernel_launch(void* const* d_in, const int* in_sizes, int n_in,
                              void* d_out, int out_size)
{
    const float* x         = (const float*)d_in[0];
    const float* lin_in_w  = (const float*)d_in[1];
    const float* lin_in_b  = (const float*)d_in[2];
    const float* W_in      = (const float*)d_in[3];
    const float* conv_w    = (const float*)d_in[4];
    const float* conv_b    = (const float*)d_in[5];
    const float* dt_bias   = (const float*)d_in[6];
    const float* A_log     = (const float*)d_in[7];
    const float* Dp        = (const float*)d_in[8];
    const float* norm_w    = (const float*)d_in[9];
    const float* W_out     = (const float*)d_in[10];
    const float* ln_w      = (const float*)d_in[11];
    const float* ln_b      = (const float*)d_in[12];
    const float* lin_out_w = (const float*)d_in[13];
    const float* lin_out_b = (const float*)d_in[14];
    float* out = (float*)d_out;

    void *ph, *phh, *pzxh, *pmh, *pxh, *pyh;
    cudaGetSymbolAddress(&ph, g_h);
    cudaGetSymbolAddress(&phh, g_hh);
    cudaGetSymbolAddress(&pzxh, g_zxh);
    cudaGetSymbolAddress(&pmh, g_mh);
    cudaGetSymbolAddress(&pxh, g_xh);
    cudaGetSymbolAddress(&pyh, g_yh);
    void *plw, *pwiw, *pwow;
    cudaGetSymbolAddress(&plw, g_linw);
    cudaGetSymbolAddress(&pwiw, g_winw);
    cudaGetSymbolAddress(&pwow, g_woutw);

    static bool attrset = false;
    if (!attrset) {
        cudaFuncSetAttribute(k_gemm_fp16,
            cudaFuncAttributeMaxDynamicSharedMemorySize, GT_SMEM);
        attrset = true;
    }

    // ---- conversions + linear_in ----
    k_cvt_x<<<NROWS*NCH/256, 256>>>(x, (__half*)pxh);
    k_cvt_w<<<dim3(DMODEL, 1), NCH>>>(lin_in_w, (__half*)plw,
        NCH, DMODEL, 0, 0);
    k_cvt_w<<<dim3(DPROJP, NLAYERS), DMODEL>>>(W_in, (__half*)pwiw,
        DMODEL, DPROJ, DMODEL*DPROJ, DPROJP*DMODEL);
    k_gemm_fp16<<<dim3(2, NROWS/128), 256, GT_SMEM>>>(
        (const __half*)pxh, (const __half*)plw,
        lin_in_b, (float*)ph, (__half*)phh, DMODEL, NCH);
    k_cvt_w<<<dim3(DMODEL, NLAYERS), DINNER>>>(W_out, (__half*)pwow,
        DINNER, DMODEL, DINNER*DMODEL, DMODEL*DINNER);

    for (int l = 0; l < NLAYERS; l++) {
        // zxbcdt (fp16 only)
        k_gemm_fp16<<<dim3(DPROJP/128, NROWS/128), 256, GT_SMEM>>>(
            (const __half*)phh,
            (const __half*)pwiw + (size_t)l*DPROJP*DMODEL,
            nullptr, nullptr, (__half*)pzxh, DPROJ, DMODEL);

        k_conv_dt<<<dim3(SEQ/TCH, BATCH), CONVDIM>>>(conv_w, conv_b, dt_bias, A_log, l);

        k_scan<<<BATCH*NHEADS*4, 256>>>(Dp, l);

        k_gate_rms<<<NROWS, 256>>>(norm_w, l);

        // m = y @ W_out (fp16 only)
        k_gemm_fp16<<<dim3(DMODEL/128, NROWS/128), 256, GT_SMEM>>>(
            (const __half*)pyh,
            (const __half*)pwow + (size_t)l*DMODEL*DINNER,
            nullptr, nullptr, (__half*)pmh, DMODEL, DINNER);

        if (l < NLAYERS - 1)
            k_res_ln<<<NROWS, 256>>>(ln_w, ln_b, l);
        else
            k_res_ln_out<<<NROWS, 256>>>(ln_w, ln_b, l,
                                         lin_out_w, lin_out_b, out);
    }
}

// round 15
// speedup vs baseline: 1.3871x; 1.3871x over previous
#include <cuda_runtime.h>
#include <cuda_fp16.h>
#include <cstdint>
#include <math.h>

// ---------------- config ----------------
#define BATCH   16
#define SEQ     2048
#define NCH     64
#define DMODEL  256
#define DINNER  512
#define DSTATE  64
#define NHEADS  8
#define HP      64
#define CONVDIM 640          // DINNER + 2*DSTATE
#define DPROJ   1160         // 2*DINNER + 2*DSTATE + NHEADS
#define NROWS   (BATCH*SEQ)  // 32768
#define NLAYERS 4
#define LN_EPS  1e-5f
#define DPROJP  1280         // DPROJ padded to 128
#define TCH     32           // conv time-chunk

// ---------------- scratch (device globals; allocation-free) ----------------
__device__ float  g_h[NROWS*DMODEL];        // residual stream (fp32)
__device__ __half g_hh[NROWS*DMODEL];       // fp16 copy of h
__device__ __half g_zxh[NROWS*DPROJ];       // zxbcdt (fp16)
__device__ __half g_xacth[NROWS*DINNER];    // silu(conv(x)) (fp16, x part only)
__device__ float  g_bcf[NROWS*2*DSTATE];    // conv'd B,C (fp32)
__device__ float2 g_dtA[NROWS*NHEADS];      // (softplus dt, exp(dt*A)) fp32
__device__ __half g_y0h[NROWS*DINNER];      // scan partial (n 0..31)
__device__ __half g_y1h[NROWS*DINNER];      // scan partial (n 32..63)
__device__ __half g_mh[NROWS*DMODEL];       // y @ W_out (fp16)

// fp16 activations (GEMM A operands)
__device__ __half g_xh[NROWS*NCH];
__device__ __half g_yh[NROWS*DINNER];

// fp16 transposed weights (GEMM B operands), [Npad][K]
__device__ __half g_linw[DMODEL*NCH];
__device__ __half g_winw[NLAYERS*DPROJP*DMODEL];
__device__ __half g_woutw[NLAYERS*DMODEL*DINNER];

__device__ __forceinline__ float siluf(float x) {
    return x * (1.f / (1.f + __expf(-x)));
}

__device__ __forceinline__ uint32_t smem_u32(const void* p) {
    uint32_t a;
    asm("{ .reg .u64 t; cvta.to.shared.u64 t, %1; cvt.u32.u64 %0, t; }"
        : "=r"(a) : "l"(p));
    return a;
}

#define LDM_X4(r0, r1, r2, r3, addr) \
    asm volatile("ldmatrix.sync.aligned.m8n8.x4.shared.b16 {%0,%1,%2,%3}, [%4];" \
        : "=r"(r0), "=r"(r1), "=r"(r2), "=r"(r3) : "r"(addr))

#define MMA_FP16(c, a, b0v, b1v) \
    asm volatile("mma.sync.aligned.m16n8k16.row.col.f32.f16.f16.f32 " \
        "{%0,%1,%2,%3}, {%4,%5,%6,%7}, {%8,%9}, {%0,%1,%2,%3};" \
        : "+f"((c)[0]), "+f"((c)[1]), "+f"((c)[2]), "+f"((c)[3]) \
        : "r"((a)[0]), "r"((a)[1]), "r"((a)[2]), "r"((a)[3]), \
          "r"(b0v), "r"(b1v))

#define CP16(dst, src) \
    asm volatile("cp.async.cg.shared.global [%0], [%1], 16;" \
        :: "r"(dst), "l"(src) : "memory")
#define CPCOMMIT() asm volatile("cp.async.commit_group;" ::: "memory")
#define CPWAIT(n)  asm volatile("cp.async.wait_group %0;" :: "n"(n) : "memory")

// ---------------- weight / input conversion ----------------
__global__ void k_cvt_w(const float* __restrict__ src, __half* __restrict__ dh,
                        int K, int N, int srcStrideLayer, int dstStrideLayer)
{
    int n = blockIdx.x;
    int l = blockIdx.y;
    int k = threadIdx.x;                 // blockDim.x == K
    float v = (n < N) ? src[(size_t)l*srcStrideLayer + (size_t)k*N + n] : 0.f;
    dh[(size_t)l*dstStrideLayer + (size_t)n*K + k] = __float2half_rn(v);
}

__global__ void k_cvt_x(const float* __restrict__ src, __half* __restrict__ d)
{
    int i = blockIdx.x * 256 + threadIdx.x;
    d[i] = __float2half_rn(src[i]);
}

// ============================================================================
// Single-pass fp16 tensor-core GEMM, CTA tile 64x128, 8 warps (4m x 2n),
// warp tile 16x64, BK=32, proven 2-stage cp.async control flow.
// Lower register footprint -> 3 CTAs/SM (occ 50%) to hide latency.
// C[M,N] = A[M,K] @ B[K,N](stored [Npad][K]) (+bias), fp32 accumulate.
// Requires M%64==0, K%32==0.
// ============================================================================
#define GSTRIDE 40
#define ATILEB  (64*GSTRIDE*2)     // 5120 B
#define BTILEB  (128*GSTRIDE*2)    // 10240 B
#define STAGEB  (ATILEB+BTILEB)    // 15360 B
#define GT_SMEM (2*STAGEB)         // 30720 B

__global__ __launch_bounds__(256, 3) void k_gemm_fp16(
    const __half* __restrict__ A, const __half* __restrict__ B,
    const float* __restrict__ bias, float* __restrict__ C,
    __half* __restrict__ Ch, int N, int K)
{
    extern __shared__ __align__(128) uint8_t dsm[];
    const uint32_t smb = smem_u32(dsm);

    int tid = threadIdx.x;
    int wid = tid >> 5, lane = tid & 31;
    int m0 = blockIdx.y * 64, n0 = blockIdx.x * 128;
    int wm = wid & 3, wn = wid >> 2;

    float acc[8][4];
#pragma unroll
    for (int nt = 0; nt < 8; nt++)
#pragma unroll
        for (int j = 0; j < 4; j++) acc[nt][j] = 0.f;

    const __half* Asrc = A + (size_t)m0 * K;
    const __half* Bsrc = B + (size_t)n0 * K;
    const int arow = tid >> 2, apart = tid & 3;   // A: 64 rows x 4 parts
    const int brow = tid >> 2, bpart = tid & 3;   // B: rows brow, brow+64

    const uint32_t aoff = (uint32_t)((wm*16 + (lane & 7) + ((lane >> 3) & 1) * 8) * (GSTRIDE*2))
                        + ((lane >> 4) & 1) * 16;
    const uint32_t boff = (uint32_t)((wn*64 + (lane & 7) + ((lane >> 4) & 1) * 8) * (GSTRIDE*2))
                        + ((lane >> 3) & 1) * 16;

    const int NC = K >> 5;

    // ---- prologue: chunk 0 -> stage 0 ----
    CP16(smb + (uint32_t)(arow * (GSTRIDE*2) + apart * 16),
         Asrc + (size_t)arow * K + apart * 8);
#pragma unroll
    for (int it = 0; it < 2; it++) {
        int r = brow + it * 64;
        CP16(smb + ATILEB + (uint32_t)(r * (GSTRIDE*2) + bpart * 16),
             Bsrc + (size_t)r * K + bpart * 8);
    }
    CPCOMMIT();

    for (int c = 0; c < NC; c++) {
        int s = c & 1;
        if (c + 1 < NC) {
            uint32_t sb2 = smb + ((c + 1) & 1) * STAGEB;
            int kb = (c + 1) * 32;
            CP16(sb2 + (uint32_t)(arow * (GSTRIDE*2) + apart * 16),
                 Asrc + (size_t)arow * K + kb + apart * 8);
#pragma unroll
            for (int it = 0; it < 2; it++) {
                int r = brow + it * 64;
                CP16(sb2 + ATILEB + (uint32_t)(r * (GSTRIDE*2) + bpart * 16),
                     Bsrc + (size_t)r * K + kb + bpart * 8);
            }
            CPCOMMIT();
            CPWAIT(1);
        } else {
            CPWAIT(0);
        }
        __syncthreads();

        uint32_t sbase = smb + s * STAGEB;
#pragma unroll
        for (int ks = 0; ks < 2; ks++) {
            uint32_t ra[4];
            LDM_X4(ra[0], ra[1], ra[2], ra[3], sbase + aoff + ks * 32);
            uint32_t rb[8][2];
            uint32_t bbase = sbase + ATILEB + boff + ks * 32;
#pragma unroll
            for (int g = 0; g < 4; g++)
                LDM_X4(rb[2*g][0], rb[2*g][1], rb[2*g+1][0], rb[2*g+1][1],
                       bbase + g * 16 * (GSTRIDE*2));
#pragma unroll
            for (int nt = 0; nt < 8; nt++)
                MMA_FP16(acc[nt], ra, rb[nt][0], rb[nt][1]);
        }
        __syncthreads();
    }

    const int gid = lane >> 2, tig = lane & 3;
#pragma unroll
    for (int nt = 0; nt < 8; nt++) {
        int col = n0 + wn * 64 + nt * 8 + tig * 2;
        if (col < N) {
            int r0 = m0 + wm * 16 + gid;
            float2 v0 = make_float2(acc[nt][0], acc[nt][1]);
            float2 v1 = make_float2(acc[nt][2], acc[nt][3]);
            if (bias) {
                float b0 = bias[col], b1 = bias[col + 1];
                v0.x += b0; v0.y += b1; v1.x += b0; v1.y += b1;
            }
            if (C) {
                *(float2*)(C + (size_t)r0 * N + col) = v0;
                *(float2*)(C + (size_t)(r0 + 8) * N + col) = v1;
            }
            if (Ch) {
                *(__half2*)(Ch + (size_t)r0 * N + col) =
                    __floats2half2_rn(v0.x, v0.y);
                *(__half2*)(Ch + (size_t)(r0 + 8) * N + col) =
                    __floats2half2_rn(v1.x, v1.y);
            }
        }
    }
}

// ------------- causal depthwise conv(4) + SiLU + dt/dA, t-chunked -------------
__global__ __launch_bounds__(CONVDIM) void k_conv_dt(
    const float* __restrict__ conv_w, const float* __restrict__ conv_b,
    const float* __restrict__ dt_bias, const float* __restrict__ A_log,
    int layer)
{
    int t0 = blockIdx.x * TCH;
    int b  = blockIdx.y;
    int c  = threadIdx.x;                  // 0..639

    const float* wr = conv_w + (size_t)layer*CONVDIM*4 + c*4;
    float w0 = wr[0], w1 = wr[1], w2 = wr[2], w3 = wr[3];
    float cb = conv_b[layer*CONVDIM + c];

    const __half* zc = g_zxh + (size_t)(b*SEQ)*DPROJ + DINNER + c;
    float h3 = 0.f, h2 = 0.f, h1 = 0.f;
    if (t0 >= 3) {
        h3 = __half2float(zc[(size_t)(t0-3)*DPROJ]);
        h2 = __half2float(zc[(size_t)(t0-2)*DPROJ]);
        h1 = __half2float(zc[(size_t)(t0-1)*DPROJ]);
    }

    float dtb = 0.f, Aneg = 0.f;
    const __half* dz = nullptr;
    if (c < NHEADS) {
        dtb  = dt_bias[layer*NHEADS + c];
        Aneg = -expf(A_log[layer*NHEADS + c]);
        dz   = g_zxh + (size_t)(b*SEQ)*DPROJ + DINNER + CONVDIM + c;
    }

    bool isx = (c < DINNER);
    __half* xo = g_xacth + (size_t)(b*SEQ + t0)*DINNER + c;
    float*  bo = g_bcf   + (size_t)(b*SEQ + t0)*(2*DSTATE) + (c - DINNER);

#pragma unroll 4
    for (int u = 0; u < TCH; u++) {
        float cur = __half2float(zc[(size_t)(t0+u)*DPROJ]);
        float s = cb + h3*w0 + h2*w1 + h1*w2 + cur*w3;
        float act = siluf(s);
        if (isx) xo[(size_t)u*DINNER] = __float2half_rn(act);
        else     bo[(size_t)u*(2*DSTATE)] = act;
        h3 = h2; h2 = h1; h1 = cur;
        if (c < NHEADS) {
            float draw = __half2float(dz[(size_t)(t0+u)*DPROJ]) + dtb;
            float dtv = (draw > 20.f) ? draw : log1pf(expf(draw));
            g_dtA[(size_t)(b*SEQ + t0 + u)*NHEADS + c] =
                make_float2(dtv, expf(dtv * Aneg));
        }
    }
}

// ---------------- sequential selective scan (round-9 proven version) ----------
__global__ __launch_bounds__(256) void k_scan(
    const float* __restrict__ Dp, int layer)
{
    int bh = blockIdx.x >> 1, half = blockIdx.x & 1;
    int b = bh >> 3, h = bh & 7;
    int tid = threadIdx.x;
    int p = tid >> 2, q = tid & 3;
    int n0 = half*32 + q*8;

    float S[8];
#pragma unroll
    for (int j = 0; j < 8; j++) S[j] = 0.f;

    float Dh = (half == 0) ? Dp[layer*NHEADS + h] : 0.f;

    const __half*  xrow = g_xacth + (size_t)(b*SEQ)*DINNER + h*HP + p;
    const float2*  dap  = g_dtA   + (size_t)(b*SEQ)*NHEADS + h;
    const float*   bcb  = g_bcf   + (size_t)(b*SEQ)*(2*DSTATE);
    __half* yp = (half == 0 ? g_y0h : g_y1h)
               + (size_t)(b*SEQ)*DINNER + h*HP + p;

    float sx[4]; float2 sda[4];
    float sB[4][8], sC[4][8];
#pragma unroll
    for (int u = 0; u < 4; u++) {
        sx[u]  = __half2float(xrow[(size_t)u*DINNER]);
        sda[u] = dap[u*NHEADS];
        const float* bc = bcb + (size_t)u*(2*DSTATE);
        ((float4*)sB[u])[0] = *(const float4*)(bc + n0);
        ((float4*)sB[u])[1] = *(const float4*)(bc + n0 + 4);
        ((float4*)sC[u])[0] = *(const float4*)(bc + DSTATE + n0);
        ((float4*)sC[u])[1] = *(const float4*)(bc + DSTATE + n0 + 4);
    }

    for (int t = 0; t < SEQ; t += 4) {
#pragma unroll
        for (int u = 0; u < 4; u++) {
            float xv = sx[u];
            float2 da = sda[u];
            float coef = da.x * xv;
            float a0 = 0.f, a1 = 0.f;
#pragma unroll
            for (int j = 0; j < 4; j++) {
                S[j] = S[j]*da.y + coef*sB[u][j];
                a0 += S[j]*sC[u][j];
            }
#pragma unroll
            for (int j = 4; j < 8; j++) {
                S[j] = S[j]*da.y + coef*sB[u][j];
                a1 += S[j]*sC[u][j];
            }
            float acc = a0 + a1;
            acc += __shfl_xor_sync(0xffffffffu, acc, 1);
            acc += __shfl_xor_sync(0xffffffffu, acc, 2);
            if (q == 0)
                yp[(size_t)(t+u)*DINNER] = __float2half_rn(acc + Dh*xv);

            int tt = t + u + 4; if (tt > SEQ - 1) tt = SEQ - 1;
            sx[u]  = __half2float(xrow[(size_t)tt*DINNER]);
            sda[u] = dap[tt*NHEADS];
            const float* bc = bcb + (size_t)tt*(2*DSTATE);
            ((float4*)sB[u])[0] = *(const float4*)(bc + n0);
            ((float4*)sB[u])[1] = *(const float4*)(bc + n0 + 4);
            ((float4*)sC[u])[0] = *(const float4*)(bc + DSTATE + n0);
            ((float4*)sC[u])[1] = *(const float4*)(bc + DSTATE + n0 + 4);
        }
    }
}

// ---------------- gated RMSNorm: y = rmsnorm((y0+y1) * silu(z)) -> fp16 ----------------
__global__ __launch_bounds__(256) void k_gate_rms(
    const float* __restrict__ norm_w, int layer)
{
    int row = blockIdx.x;
    int tid = threadIdx.x;
    int lane = tid & 31, wid = tid >> 5;
    __shared__ float red[8];

    const __half* zrow = g_zxh + (size_t)row*DPROJ;
    size_t base = (size_t)row*DINNER;

    float y0a = __half2float(g_y0h[base + tid])       + __half2float(g_y1h[base + tid]);
    float y1a = __half2float(g_y0h[base + tid + 256]) + __half2float(g_y1h[base + tid + 256]);
    float v0 = y0a * siluf(__half2float(zrow[tid]));
    float v1 = y1a * siluf(__half2float(zrow[tid + 256]));
    float s = v0*v0 + v1*v1;
#pragma unroll
    for (int o = 16; o > 0; o >>= 1) s += __shfl_xor_sync(0xffffffffu, s, o);
    if (lane == 0) red[wid] = s;
    __syncthreads();
    if (tid < 32) {
        float v = (lane < 8) ? red[lane] : 0.f;
#pragma unroll
        for (int o = 4; o > 0; o >>= 1) v += __shfl_xor_sync(0xffffffffu, v, o);
        if (lane == 0) red[0] = v;
    }
    __syncthreads();
    float scale = rsqrtf(red[0] * (1.f/DINNER) + LN_EPS);
    g_yh[base + tid]       = __float2half_rn(v0 * scale * norm_w[layer*DINNER + tid]);
    g_yh[base + tid + 256] = __float2half_rn(v1 * scale * norm_w[layer*DINNER + tid + 256]);
}

// ---------------- residual + LayerNorm: h = LN(m + h) -> fp32 + fp16 ----------------
__global__ __launch_bounds__(256) void k_res_ln(
    const float* __restrict__ ln_w, const float* __restrict__ ln_b, int layer)
{
    int row = blockIdx.x;
    int tid = threadIdx.x;
    int lane = tid & 31, wid = tid >> 5;
    __shared__ float red1[8], red2[8];

    size_t o = (size_t)row*DMODEL + tid;
    float u = __half2float(g_mh[o]) + g_h[o];
    float s1 = u, s2 = u*u;
#pragma unroll
    for (int ofs = 16; ofs > 0; ofs >>= 1) {
        s1 += __shfl_xor_sync(0xffffffffu, s1, ofs);
        s2 += __shfl_xor_sync(0xffffffffu, s2, ofs);
    }
    if (lane == 0) { red1[wid] = s1; red2[wid] = s2; }
    __syncthreads();
    if (tid < 32) {
        float a = (lane < 8) ? red1[lane] : 0.f;
        float c = (lane < 8) ? red2[lane] : 0.f;
#pragma unroll
        for (int ofs = 4; ofs > 0; ofs >>= 1) {
            a += __shfl_xor_sync(0xffffffffu, a, ofs);
            c += __shfl_xor_sync(0xffffffffu, c, ofs);
        }
        if (lane == 0) { red1[0] = a; red2[0] = c; }
    }
    __syncthreads();
    float mu  = red1[0] * (1.f/DMODEL);
    float var = red2[0] * (1.f/DMODEL) - mu*mu;
    float outv = (u - mu) * rsqrtf(var + LN_EPS) * ln_w[layer*DMODEL + tid]
               + ln_b[layer*DMODEL + tid];
    g_h[o]  = outv;
    g_hh[o] = __float2half_rn(outv);
}

// ---- final layer: residual + LayerNorm + linear_out fused -> d_out ----
__global__ __launch_bounds__(256) void k_res_ln_out(
    const float* __restrict__ ln_w, const float* __restrict__ ln_b, int layer,
    const float* __restrict__ w, const float* __restrict__ bias,
    float* __restrict__ out)
{
    int row = blockIdx.x;
    int tid = threadIdx.x;
    int lane = tid & 31, wid = tid >> 5;
    __shared__ float red1[8], red2[8];
    __shared__ float red5[8][5];

    size_t o = (size_t)row*DMODEL + tid;
    float u = __half2float(g_mh[o]) + g_h[o];
    float s1 = u, s2 = u*u;
#pragma unroll
    for (int ofs = 16; ofs > 0; ofs >>= 1) {
        s1 += __shfl_xor_sync(0xffffffffu, s1, ofs);
        s2 += __shfl_xor_sync(0xffffffffu, s2, ofs);
    }
    if (lane == 0) { red1[wid] = s1; red2[wid] = s2; }
    __syncthreads();
    if (tid < 32) {
        float a = (lane < 8) ? red1[lane] : 0.f;
        float c = (lane < 8) ? red2[lane] : 0.f;
#pragma unroll
        for (int ofs = 4; ofs > 0; ofs >>= 1) {
            a += __shfl_xor_sync(0xffffffffu, a, ofs);
            c += __shfl_xor_sync(0xffffffffu, c, ofs);
        }
        if (lane == 0) { red1[0] = a; red2[0] = c; }
    }
    __syncthreads();
    float mu  = red1[0] * (1.f/DMODEL);
    float var = red2[0] * (1.f/DMODEL) - mu*mu;
    float outv = (u - mu) * rsqrtf(var + LN_EPS) * ln_w[layer*DMODEL + tid]
               + ln_b[layer*DMODEL + tid];

    float a0 = outv * w[tid*5 + 0];
    float a1 = outv * w[tid*5 + 1];
    float a2 = outv * w[tid*5 + 2];
    float a3 = outv * w[tid*5 + 3];
    float a4 = outv * w[tid*5 + 4];
#pragma unroll
    for (int ofs = 16; ofs > 0; ofs >>= 1) {
        a0 += __shfl_xor_sync(0xffffffffu, a0, ofs);
        a1 += __shfl_xor_sync(0xffffffffu, a1, ofs);
        a2 += __shfl_xor_sync(0xffffffffu, a2, ofs);
        a3 += __shfl_xor_sync(0xffffffffu, a3, ofs);
        a4 += __shfl_xor_sync(0xffffffffu, a4, ofs);
    }
    if (lane == 0) {
        red5[wid][0] = a0; red5[wid][1] = a1; red5[wid][2] = a2;
        red5[wid][3] = a3; red5[wid][4] = a4;
    }
    __syncthreads();
    if (tid < 5) {
        float s = 0.f;
#pragma unroll
        for (int j = 0; j < 8; j++) s += red5[j][tid];
        out[(size_t)row*5 + tid] = s + bias[tid];
    }
}

// ---------------- launcher ----------------
extern "C" void kernel_launch(void* const* d_in, const int* in_sizes, int n_in,
                              void* d_out, int out_size)
{
    const float* x         = (const float*)d_in[0];
    const float* lin_in_w  = (const float*)d_in[1];
    const float* lin_in_b  = (const float*)d_in[2];
    const float* W_in      = (const float*)d_in[3];
    const float* conv_w    = (const float*)d_in[4];
    const float* conv_b    = (const float*)d_in[5];
    const float* dt_bias   = (const float*)d_in[6];
    const float* A_log     = (const float*)d_in[7];
    const float* Dp        = (const float*)d_in[8];
    const float* norm_w    = (const float*)d_in[9];
    const float* W_out     = (const float*)d_in[10];
    const float* ln_w      = (const float*)d_in[11];
    const float* ln_b      = (const float*)d_in[12];
    const float* lin_out_w = (const float*)d_in[13];
    const float* lin_out_b = (const float*)d_in[14];
    float* out = (float*)d_out;

    void *ph, *phh, *pzxh, *pmh, *pxh, *pyh;
    cudaGetSymbolAddress(&ph, g_h);
    cudaGetSymbolAddress(&phh, g_hh);
    cudaGetSymbolAddress(&pzxh, g_zxh);
    cudaGetSymbolAddress(&pmh, g_mh);
    cudaGetSymbolAddress(&pxh, g_xh);
    cudaGetSymbolAddress(&pyh, g_yh);
    void *plw, *pwiw, *pwow;
    cudaGetSymbolAddress(&plw, g_linw);
    cudaGetSymbolAddress(&pwiw, g_winw);
    cudaGetSymbolAddress(&pwow, g_woutw);

    static bool attrset = false;
    if (!attrset) {
        cudaFuncSetAttribute(k_gemm_fp16,
            cudaFuncAttributeMaxDynamicSharedMemorySize, GT_SMEM);
        attrset = true;
    }

    // ---- conversions + linear_in (launch index 3 = GEMM for ncu) ----
    k_cvt_x<<<NROWS*NCH/256, 256>>>(x, (__half*)pxh);
    k_cvt_w<<<dim3(DMODEL, 1), NCH>>>(lin_in_w, (__half*)plw,
        NCH, DMODEL, 0, 0);
    k_cvt_w<<<dim3(DPROJP, NLAYERS), DMODEL>>>(W_in, (__half*)pwiw,
        DMODEL, DPROJ, DMODEL*DPROJ, DPROJP*DMODEL);
    k_gemm_fp16<<<dim3(2, NROWS/64), 256, GT_SMEM>>>(
        (const __half*)pxh, (const __half*)plw,
        lin_in_b, (float*)ph, (__half*)phh, DMODEL, NCH);
    k_cvt_w<<<dim3(DMODEL, NLAYERS), DINNER>>>(W_out, (__half*)pwow,
        DINNER, DMODEL, DINNER*DMODEL, DMODEL*DINNER);

    for (int l = 0; l < NLAYERS; l++) {
        // zxbcdt (fp16 only)
        k_gemm_fp16<<<dim3(DPROJP/128, NROWS/64), 256, GT_SMEM>>>(
            (const __half*)phh,
            (const __half*)pwiw + (size_t)l*DPROJP*DMODEL,
            nullptr, nullptr, (__half*)pzxh, DPROJ, DMODEL);

        k_conv_dt<<<dim3(SEQ/TCH, BATCH), CONVDIM>>>(conv_w, conv_b, dt_bias, A_log, l);

        k_scan<<<BATCH*NHEADS*2, 256>>>(Dp, l);

        k_gate_rms<<<NROWS, 256>>>(norm_w, l);

        // m = y @ W_out (fp16 only)
        k_gemm_fp16<<<dim3(DMODEL/128, NROWS/64), 256, GT_SMEM>>>(
            (const __half*)pyh,
            (const __half*)pwow + (size_t)l*DMODEL*DINNER,
            nullptr, nullptr, (__half*)pmh, DMODEL, DINNER);

        if (l < NLAYERS - 1)
            k_res_ln<<<NROWS, 256>>>(ln_w, ln_b, l);
        else
            k_res_ln_out<<<NROWS, 256>>>(ln_w, ln_b, l,
                                         lin_out_w, lin_out_b, out);
    }
}

// round 16
// speedup vs baseline: 1.4241x; 1.0267x over previous
#include <cuda_runtime.h>
#include <cuda_fp16.h>
#include <cstdint>
#include <math.h>

// ---------------- config ----------------
#define BATCH   16
#define SEQ     2048
#define NCH     64
#define DMODEL  256
#define DINNER  512
#define DSTATE  64
#define NHEADS  8
#define HP      64
#define CONVDIM 640          // DINNER + 2*DSTATE
#define DPROJ   1160         // 2*DINNER + 2*DSTATE + NHEADS
#define NROWS   (BATCH*SEQ)  // 32768
#define NLAYERS 4
#define LN_EPS  1e-5f
#define DPROJP  1280         // DPROJ padded to 128
#define TCH     32           // conv time-chunk

// ---------------- scratch (device globals; allocation-free) ----------------
__device__ __half g_hh[NROWS*DMODEL];       // residual stream (fp16)
__device__ __half g_zxh[NROWS*DPROJ];       // zxbcdt (fp16)
__device__ __half g_xacth[NROWS*DINNER];    // silu(conv(x)) (fp16, x part only)
__device__ float  g_bcf[NROWS*2*DSTATE];    // conv'd B,C (fp32)
__device__ float2 g_dtA[NROWS*NHEADS];      // (softplus dt, exp(dt*A)) fp32
__device__ __half g_y0h[NROWS*DINNER];      // scan partial (n 0..31)
__device__ __half g_y1h[NROWS*DINNER];      // scan partial (n 32..63)
__device__ __half g_mh[NROWS*DMODEL];       // y @ W_out (fp16)

// fp16 activations (GEMM A operands)
__device__ __half g_xh[NROWS*NCH];
__device__ __half g_yh[NROWS*DINNER];

// fp16 transposed weights (GEMM B operands), [Npad][K]
__device__ __half g_linw[DMODEL*NCH];
__device__ __half g_winw[NLAYERS*DPROJP*DMODEL];
__device__ __half g_woutw[NLAYERS*DMODEL*DINNER];

__device__ __forceinline__ float siluf(float x) {
    return x * (1.f / (1.f + __expf(-x)));
}

__device__ __forceinline__ uint32_t smem_u32(const void* p) {
    uint32_t a;
    asm("{ .reg .u64 t; cvta.to.shared.u64 t, %1; cvt.u32.u64 %0, t; }"
        : "=r"(a) : "l"(p));
    return a;
}

#define LDM_X4(r0, r1, r2, r3, addr) \
    asm volatile("ldmatrix.sync.aligned.m8n8.x4.shared.b16 {%0,%1,%2,%3}, [%4];" \
        : "=r"(r0), "=r"(r1), "=r"(r2), "=r"(r3) : "r"(addr))

#define MMA_FP16(c, a, b0v, b1v) \
    asm volatile("mma.sync.aligned.m16n8k16.row.col.f32.f16.f16.f32 " \
        "{%0,%1,%2,%3}, {%4,%5,%6,%7}, {%8,%9}, {%0,%1,%2,%3};" \
        : "+f"((c)[0]), "+f"((c)[1]), "+f"((c)[2]), "+f"((c)[3]) \
        : "r"((a)[0]), "r"((a)[1]), "r"((a)[2]), "r"((a)[3]), \
          "r"(b0v), "r"(b1v))

#define CP16(dst, src) \
    asm volatile("cp.async.cg.shared.global [%0], [%1], 16;" \
        :: "r"(dst), "l"(src) : "memory")
#define CPCOMMIT() asm volatile("cp.async.commit_group;" ::: "memory")
#define CPWAIT(n)  asm volatile("cp.async.wait_group %0;" :: "n"(n) : "memory")

// ---------------- weight / input conversion ----------------
__global__ void k_cvt_w(const float* __restrict__ src, __half* __restrict__ dh,
                        int K, int N, int srcStrideLayer, int dstStrideLayer)
{
    int n = blockIdx.x;
    int l = blockIdx.y;
    int k = threadIdx.x;                 // blockDim.x == K
    float v = (n < N) ? src[(size_t)l*srcStrideLayer + (size_t)k*N + n] : 0.f;
    dh[(size_t)l*dstStrideLayer + (size_t)n*K + k] = __float2half_rn(v);
}

__global__ void k_cvt_x(const float* __restrict__ src, __half* __restrict__ d)
{
    int i = blockIdx.x * 256 + threadIdx.x;
    d[i] = __float2half_rn(src[i]);
}

// ============================================================================
// Single-pass fp16 tensor-core GEMM (round-9 proven 2-stage version)
// C[M,N] = A[M,K] @ B[K,N](stored [Npad][K]) (+bias), fp32 accumulate.
// CTA 128x128, BK=32, 8 warps (4m x 2n), 2-stage cp.async pipeline.
// ============================================================================
#define GSTRIDE 40
#define TILEB   (128*GSTRIDE*2)
#define STAGEB  (2*TILEB)
#define GT_SMEM (2*STAGEB)

__global__ __launch_bounds__(256, 2) void k_gemm_fp16(
    const __half* __restrict__ A, const __half* __restrict__ B,
    const float* __restrict__ bias, float* __restrict__ C,
    __half* __restrict__ Ch, int N, int K)
{
    extern __shared__ __align__(128) uint8_t dsm[];
    const uint32_t smb = smem_u32(dsm);

    int tid = threadIdx.x;
    int wid = tid >> 5, lane = tid & 31;
    int m0 = blockIdx.y * 128, n0 = blockIdx.x * 128;
    int wm = wid & 3, wn = wid >> 2;

    float acc[2][8][4];
#pragma unroll
    for (int mt = 0; mt < 2; mt++)
#pragma unroll
        for (int nt = 0; nt < 8; nt++)
#pragma unroll
            for (int j = 0; j < 4; j++) acc[mt][nt][j] = 0.f;

    const __half* srcs[2] = { A + (size_t)m0 * K, B + (size_t)n0 * K };
    const int row0 = tid >> 2, part = tid & 3;

    const uint32_t aoff = (uint32_t)((wm*32 + (lane & 7) + ((lane >> 3) & 1) * 8) * (GSTRIDE*2))
                        + ((lane >> 4) & 1) * 16;
    const uint32_t boff = (uint32_t)((wn*64 + (lane & 7) + ((lane >> 4) & 1) * 8) * (GSTRIDE*2))
                        + ((lane >> 3) & 1) * 16;

    const int NC = K >> 5;

#pragma unroll
    for (int t = 0; t < 2; t++) {
#pragma unroll
        for (int it = 0; it < 2; it++) {
            int r = row0 + it * 64;
            uint32_t d = smb + t * TILEB + (uint32_t)(r * (GSTRIDE*2) + part * 16);
            CP16(d, srcs[t] + (size_t)r * K + part * 8);
        }
    }
    CPCOMMIT();

    for (int c = 0; c < NC; c++) {
        int s = c & 1;
        if (c + 1 < NC) {
            uint32_t sb2 = smb + ((c + 1) & 1) * STAGEB;
            int kb = (c + 1) * 32;
#pragma unroll
            for (int t = 0; t < 2; t++) {
#pragma unroll
                for (int it = 0; it < 2; it++) {
                    int r = row0 + it * 64;
                    uint32_t d = sb2 + t * TILEB + (uint32_t)(r * (GSTRIDE*2) + part * 16);
                    CP16(d, srcs[t] + (size_t)r * K + kb + part * 8);
                }
            }
            CPCOMMIT();
            CPWAIT(1);
        } else {
            CPWAIT(0);
        }
        __syncthreads();

        uint32_t sbase = smb + s * STAGEB;
#pragma unroll
        for (int ks = 0; ks < 2; ks++) {
            uint32_t abase = sbase + aoff + ks * 32;
            uint32_t ra[2][4];
            LDM_X4(ra[0][0], ra[0][1], ra[0][2], ra[0][3], abase);
            LDM_X4(ra[1][0], ra[1][1], ra[1][2], ra[1][3],
                   abase + 16 * (GSTRIDE*2));
            uint32_t rb[8][2];
            uint32_t bbase = sbase + TILEB + boff + ks * 32;
#pragma unroll
            for (int g = 0; g < 4; g++)
                LDM_X4(rb[2*g][0], rb[2*g][1], rb[2*g+1][0], rb[2*g+1][1],
                       bbase + g * 16 * (GSTRIDE*2));
#pragma unroll
            for (int mt = 0; mt < 2; mt++)
#pragma unroll
                for (int nt = 0; nt < 8; nt++)
                    MMA_FP16(acc[mt][nt], ra[mt], rb[nt][0], rb[nt][1]);
        }
        __syncthreads();
    }

    const int gid = lane >> 2, tig = lane & 3;
#pragma unroll
    for (int mt = 0; mt < 2; mt++) {
#pragma unroll
        for (int nt = 0; nt < 8; nt++) {
            int col = n0 + wn * 64 + nt * 8 + tig * 2;
            if (col < N) {
                int r0 = m0 + wm * 32 + mt * 16 + gid;
                float2 v0 = make_float2(acc[mt][nt][0], acc[mt][nt][1]);
                float2 v1 = make_float2(acc[mt][nt][2], acc[mt][nt][3]);
                if (bias) {
                    float b0 = bias[col], b1 = bias[col + 1];
                    v0.x += b0; v0.y += b1; v1.x += b0; v1.y += b1;
                }
                if (C) {
                    *(float2*)(C + (size_t)r0 * N + col) = v0;
                    *(float2*)(C + (size_t)(r0 + 8) * N + col) = v1;
                }
                if (Ch) {
                    *(__half2*)(Ch + (size_t)r0 * N + col) =
                        __floats2half2_rn(v0.x, v0.y);
                    *(__half2*)(Ch + (size_t)(r0 + 8) * N + col) =
                        __floats2half2_rn(v1.x, v1.y);
                }
            }
        }
    }
}

// ------------- causal depthwise conv(4) + SiLU + dt/dA, t-chunked -------------
__global__ __launch_bounds__(CONVDIM) void k_conv_dt(
    const float* __restrict__ conv_w, const float* __restrict__ conv_b,
    const float* __restrict__ dt_bias, const float* __restrict__ A_log,
    int layer)
{
    int t0 = blockIdx.x * TCH;
    int b  = blockIdx.y;
    int c  = threadIdx.x;                  // 0..639

    const float* wr = conv_w + (size_t)layer*CONVDIM*4 + c*4;
    float w0 = wr[0], w1 = wr[1], w2 = wr[2], w3 = wr[3];
    float cb = conv_b[layer*CONVDIM + c];

    const __half* zc = g_zxh + (size_t)(b*SEQ)*DPROJ + DINNER + c;
    float h3 = 0.f, h2 = 0.f, h1 = 0.f;
    if (t0 >= 3) {
        h3 = __half2float(zc[(size_t)(t0-3)*DPROJ]);
        h2 = __half2float(zc[(size_t)(t0-2)*DPROJ]);
        h1 = __half2float(zc[(size_t)(t0-1)*DPROJ]);
    }

    float dtb = 0.f, Aneg = 0.f;
    const __half* dz = nullptr;
    if (c < NHEADS) {
        dtb  = dt_bias[layer*NHEADS + c];
        Aneg = -expf(A_log[layer*NHEADS + c]);
        dz   = g_zxh + (size_t)(b*SEQ)*DPROJ + DINNER + CONVDIM + c;
    }

    bool isx = (c < DINNER);
    __half* xo = g_xacth + (size_t)(b*SEQ + t0)*DINNER + c;
    float*  bo = g_bcf   + (size_t)(b*SEQ + t0)*(2*DSTATE) + (c - DINNER);

#pragma unroll 4
    for (int u = 0; u < TCH; u++) {
        float cur = __half2float(zc[(size_t)(t0+u)*DPROJ]);
        float s = cb + h3*w0 + h2*w1 + h1*w2 + cur*w3;
        float act = siluf(s);
        if (isx) xo[(size_t)u*DINNER] = __float2half_rn(act);
        else     bo[(size_t)u*(2*DSTATE)] = act;
        h3 = h2; h2 = h1; h1 = cur;
        if (c < NHEADS) {
            float draw = __half2float(dz[(size_t)(t0+u)*DPROJ]) + dtb;
            float dtv = (draw > 20.f) ? draw : log1pf(expf(draw));
            g_dtA[(size_t)(b*SEQ + t0 + u)*NHEADS + c] =
                make_float2(dtv, expf(dtv * Aneg));
        }
    }
}

// ---------------- sequential selective scan (round-9 proven version) ----------
__global__ __launch_bounds__(256) void k_scan(
    const float* __restrict__ Dp, int layer)
{
    int bh = blockIdx.x >> 1, half = blockIdx.x & 1;
    int b = bh >> 3, h = bh & 7;
    int tid = threadIdx.x;
    int p = tid >> 2, q = tid & 3;
    int n0 = half*32 + q*8;

    float S[8];
#pragma unroll
    for (int j = 0; j < 8; j++) S[j] = 0.f;

    float Dh = (half == 0) ? Dp[layer*NHEADS + h] : 0.f;

    const __half*  xrow = g_xacth + (size_t)(b*SEQ)*DINNER + h*HP + p;
    const float2*  dap  = g_dtA   + (size_t)(b*SEQ)*NHEADS + h;
    const float*   bcb  = g_bcf   + (size_t)(b*SEQ)*(2*DSTATE);
    __half* yp = (half == 0 ? g_y0h : g_y1h)
               + (size_t)(b*SEQ)*DINNER + h*HP + p;

    float sx[4]; float2 sda[4];
    float sB[4][8], sC[4][8];
#pragma unroll
    for (int u = 0; u < 4; u++) {
        sx[u]  = __half2float(xrow[(size_t)u*DINNER]);
        sda[u] = dap[u*NHEADS];
        const float* bc = bcb + (size_t)u*(2*DSTATE);
        ((float4*)sB[u])[0] = *(const float4*)(bc + n0);
        ((float4*)sB[u])[1] = *(const float4*)(bc + n0 + 4);
        ((float4*)sC[u])[0] = *(const float4*)(bc + DSTATE + n0);
        ((float4*)sC[u])[1] = *(const float4*)(bc + DSTATE + n0 + 4);
    }

    for (int t = 0; t < SEQ; t += 4) {
#pragma unroll
        for (int u = 0; u < 4; u++) {
            float xv = sx[u];
            float2 da = sda[u];
            float coef = da.x * xv;
            float a0 = 0.f, a1 = 0.f;
#pragma unroll
            for (int j = 0; j < 4; j++) {
                S[j] = S[j]*da.y + coef*sB[u][j];
                a0 += S[j]*sC[u][j];
            }
#pragma unroll
            for (int j = 4; j < 8; j++) {
                S[j] = S[j]*da.y + coef*sB[u][j];
                a1 += S[j]*sC[u][j];
            }
            float acc = a0 + a1;
            acc += __shfl_xor_sync(0xffffffffu, acc, 1);
            acc += __shfl_xor_sync(0xffffffffu, acc, 2);
            if (q == 0)
                yp[(size_t)(t+u)*DINNER] = __float2half_rn(acc + Dh*xv);

            int tt = t + u + 4; if (tt > SEQ - 1) tt = SEQ - 1;
            sx[u]  = __half2float(xrow[(size_t)tt*DINNER]);
            sda[u] = dap[tt*NHEADS];
            const float* bc = bcb + (size_t)tt*(2*DSTATE);
            ((float4*)sB[u])[0] = *(const float4*)(bc + n0);
            ((float4*)sB[u])[1] = *(const float4*)(bc + n0 + 4);
            ((float4*)sC[u])[0] = *(const float4*)(bc + DSTATE + n0);
            ((float4*)sC[u])[1] = *(const float4*)(bc + DSTATE + n0 + 4);
        }
    }
}

// ---------------- gated RMSNorm: y = rmsnorm((y0+y1) * silu(z)) -> fp16 ----------------
__global__ __launch_bounds__(256) void k_gate_rms(
    const float* __restrict__ norm_w, int layer)
{
    int row = blockIdx.x;
    int tid = threadIdx.x;
    int lane = tid & 31, wid = tid >> 5;
    __shared__ float red[8];

    const __half* zrow = g_zxh + (size_t)row*DPROJ;
    size_t base = (size_t)row*DINNER;

    float y0a = __half2float(g_y0h[base + tid])       + __half2float(g_y1h[base + tid]);
    float y1a = __half2float(g_y0h[base + tid + 256]) + __half2float(g_y1h[base + tid + 256]);
    float v0 = y0a * siluf(__half2float(zrow[tid]));
    float v1 = y1a * siluf(__half2float(zrow[tid + 256]));
    float s = v0*v0 + v1*v1;
#pragma unroll
    for (int o = 16; o > 0; o >>= 1) s += __shfl_xor_sync(0xffffffffu, s, o);
    if (lane == 0) red[wid] = s;
    __syncthreads();
    if (tid < 32) {
        float v = (lane < 8) ? red[lane] : 0.f;
#pragma unroll
        for (int o = 4; o > 0; o >>= 1) v += __shfl_xor_sync(0xffffffffu, v, o);
        if (lane == 0) red[0] = v;
    }
    __syncthreads();
    float scale = rsqrtf(red[0] * (1.f/DINNER) + LN_EPS);
    g_yh[base + tid]       = __float2half_rn(v0 * scale * norm_w[layer*DINNER + tid]);
    g_yh[base + tid + 256] = __float2half_rn(v1 * scale * norm_w[layer*DINNER + tid + 256]);
}

// ------- residual + LayerNorm: h = LN(m + h), fp16 residual stream -------
__global__ __launch_bounds__(256) void k_res_ln(
    const float* __restrict__ ln_w, const float* __restrict__ ln_b, int layer)
{
    int row = blockIdx.x;
    int tid = threadIdx.x;
    int lane = tid & 31, wid = tid >> 5;
    __shared__ float red1[8], red2[8];

    size_t o = (size_t)row*DMODEL + tid;
    float u = __half2float(g_mh[o]) + __half2float(g_hh[o]);
    float s1 = u, s2 = u*u;
#pragma unroll
    for (int ofs = 16; ofs > 0; ofs >>= 1) {
        s1 += __shfl_xor_sync(0xffffffffu, s1, ofs);
        s2 += __shfl_xor_sync(0xffffffffu, s2, ofs);
    }
    if (lane == 0) { red1[wid] = s1; red2[wid] = s2; }
    __syncthreads();
    if (tid < 32) {
        float a = (lane < 8) ? red1[lane] : 0.f;
        float c = (lane < 8) ? red2[lane] : 0.f;
#pragma unroll
        for (int ofs = 4; ofs > 0; ofs >>= 1) {
            a += __shfl_xor_sync(0xffffffffu, a, ofs);
            c += __shfl_xor_sync(0xffffffffu, c, ofs);
        }
        if (lane == 0) { red1[0] = a; red2[0] = c; }
    }
    __syncthreads();
    float mu  = red1[0] * (1.f/DMODEL);
    float var = red2[0] * (1.f/DMODEL) - mu*mu;
    float outv = (u - mu) * rsqrtf(var + LN_EPS) * ln_w[layer*DMODEL + tid]
               + ln_b[layer*DMODEL + tid];
    g_hh[o] = __float2half_rn(outv);
}

// ---- final layer: residual + LayerNorm + linear_out fused -> d_out ----
__global__ __launch_bounds__(256) void k_res_ln_out(
    const float* __restrict__ ln_w, const float* __restrict__ ln_b, int layer,
    const float* __restrict__ w, const float* __restrict__ bias,
    float* __restrict__ out)
{
    int row = blockIdx.x;
    int tid = threadIdx.x;
    int lane = tid & 31, wid = tid >> 5;
    __shared__ float red1[8], red2[8];
    __shared__ float red5[8][5];

    size_t o = (size_t)row*DMODEL + tid;
    float u = __half2float(g_mh[o]) + __half2float(g_hh[o]);
    float s1 = u, s2 = u*u;
#pragma unroll
    for (int ofs = 16; ofs > 0; ofs >>= 1) {
        s1 += __shfl_xor_sync(0xffffffffu, s1, ofs);
        s2 += __shfl_xor_sync(0xffffffffu, s2, ofs);
    }
    if (lane == 0) { red1[wid] = s1; red2[wid] = s2; }
    __syncthreads();
    if (tid < 32) {
        float a = (lane < 8) ? red1[lane] : 0.f;
        float c = (lane < 8) ? red2[lane] : 0.f;
#pragma unroll
        for (int ofs = 4; ofs > 0; ofs >>= 1) {
            a += __shfl_xor_sync(0xffffffffu, a, ofs);
            c += __shfl_xor_sync(0xffffffffu, c, ofs);
        }
        if (lane == 0) { red1[0] = a; red2[0] = c; }
    }
    __syncthreads();
    float mu  = red1[0] * (1.f/DMODEL);
    float var = red2[0] * (1.f/DMODEL) - mu*mu;
    float outv = (u - mu) * rsqrtf(var + LN_EPS) * ln_w[layer*DMODEL + tid]
               + ln_b[layer*DMODEL + tid];

    float a0 = outv * w[tid*5 + 0];
    float a1 = outv * w[tid*5 + 1];
    float a2 = outv * w[tid*5 + 2];
    float a3 = outv * w[tid*5 + 3];
    float a4 = outv * w[tid*5 + 4];
#pragma unroll
    for (int ofs = 16; ofs > 0; ofs >>= 1) {
        a0 += __shfl_xor_sync(0xffffffffu, a0, ofs);
        a1 += __shfl_xor_sync(0xffffffffu, a1, ofs);
        a2 += __shfl_xor_sync(0xffffffffu, a2, ofs);
        a3 += __shfl_xor_sync(0xffffffffu, a3, ofs);
        a4 += __shfl_xor_sync(0xffffffffu, a4, ofs);
    }
    if (lane == 0) {
        red5[wid][0] = a0; red5[wid][1] = a1; red5[wid][2] = a2;
        red5[wid][3] = a3; red5[wid][4] = a4;
    }
    __syncthreads();
    if (tid < 5) {
        float s = 0.f;
#pragma unroll
        for (int j = 0; j < 8; j++) s += red5[j][tid];
        out[(size_t)row*5 + tid] = s + bias[tid];
    }
}

// ---------------- launcher ----------------
extern "C" void kernel_launch(void* const* d_in, const int* in_sizes, int n_in,
                              void* d_out, int out_size)
{
    const float* x         = (const float*)d_in[0];
    const float* lin_in_w  = (const float*)d_in[1];
    const float* lin_in_b  = (const float*)d_in[2];
    const float* W_in      = (const float*)d_in[3];
    const float* conv_w    = (const float*)d_in[4];
    const float* conv_b    = (const float*)d_in[5];
    const float* dt_bias   = (const float*)d_in[6];
    const float* A_log     = (const float*)d_in[7];
    const float* Dp        = (const float*)d_in[8];
    const float* norm_w    = (const float*)d_in[9];
    const float* W_out     = (const float*)d_in[10];
    const float* ln_w      = (const float*)d_in[11];
    const float* ln_b      = (const float*)d_in[12];
    const float* lin_out_w = (const float*)d_in[13];
    const float* lin_out_b = (const float*)d_in[14];
    float* out = (float*)d_out;

    void *phh, *pzxh, *pmh, *pxh, *pyh;
    cudaGetSymbolAddress(&phh, g_hh);
    cudaGetSymbolAddress(&pzxh, g_zxh);
    cudaGetSymbolAddress(&pmh, g_mh);
    cudaGetSymbolAddress(&pxh, g_xh);
    cudaGetSymbolAddress(&pyh, g_yh);
    void *plw, *pwiw, *pwow;
    cudaGetSymbolAddress(&plw, g_linw);
    cudaGetSymbolAddress(&pwiw, g_winw);
    cudaGetSymbolAddress(&pwow, g_woutw);

    static bool attrset = false;
    if (!attrset) {
        cudaFuncSetAttribute(k_gemm_fp16,
            cudaFuncAttributeMaxDynamicSharedMemorySize, GT_SMEM);
        attrset = true;
    }

    // ---- conversions + linear_in (launch index 3 = GEMM for ncu) ----
    k_cvt_x<<<NROWS*NCH/256, 256>>>(x, (__half*)pxh);
    k_cvt_w<<<dim3(DMODEL, 1), NCH>>>(lin_in_w, (__half*)plw,
        NCH, DMODEL, 0, 0);
    k_cvt_w<<<dim3(DPROJP, NLAYERS), DMODEL>>>(W_in, (__half*)pwiw,
        DMODEL, DPROJ, DMODEL*DPROJ, DPROJP*DMODEL);
    k_gemm_fp16<<<dim3(2, NROWS/128), 256, GT_SMEM>>>(
        (const __half*)pxh, (const __half*)plw,
        lin_in_b, nullptr, (__half*)phh, DMODEL, NCH);
    k_cvt_w<<<dim3(DMODEL, NLAYERS), DINNER>>>(W_out, (__half*)pwow,
        DINNER, DMODEL, DINNER*DMODEL, DMODEL*DINNER);

    for (int l = 0; l < NLAYERS; l++) {
        // zxbcdt (fp16 only)
        k_gemm_fp16<<<dim3(DPROJP/128, NROWS/128), 256, GT_SMEM>>>(
            (const __half*)phh,
            (const __half*)pwiw + (size_t)l*DPROJP*DMODEL,
            nullptr, nullptr, (__half*)pzxh, DPROJ, DMODEL);

        k_conv_dt<<<dim3(SEQ/TCH, BATCH), CONVDIM>>>(conv_w, conv_b, dt_bias, A_log, l);

        k_scan<<<BATCH*NHEADS*2, 256>>>(Dp, l);

        k_gate_rms<<<NROWS, 256>>>(norm_w, l);

        // m = y @ W_out (fp16 only)
        k_gemm_fp16<<<dim3(DMODEL/128, NROWS/128), 256, GT_SMEM>>>(
            (const __half*)pyh,
            (const __half*)pwow + (size_t)l*DMODEL*DINNER,
            nullptr, nullptr, (__half*)pmh, DMODEL, DINNER);

        if (l < NLAYERS - 1)
            k_res_ln<<<NROWS, 256>>>(ln_w, ln_b, l);
        else
            k_res_ln_out<<<NROWS, 256>>>(ln_w, ln_b, l,
                                         lin_out_w, lin_out_b, out);
    }
}

// round 17
// speedup vs baseline: 1.5038x; 1.0560x over previous
#include <cuda_runtime.h>
#include <cuda_fp16.h>
#include <cstdint>
#include <math.h>

// ---------------- config ----------------
#define BATCH   16
#define SEQ     2048
#define NCH     64
#define DMODEL  256
#define DINNER  512
#define DSTATE  64
#define NHEADS  8
#define HP      64
#define CONVDIM 640          // DINNER + 2*DSTATE
#define DPROJ   1160         // 2*DINNER + 2*DSTATE + NHEADS
#define NROWS   (BATCH*SEQ)  // 32768
#define NLAYERS 4
#define LN_EPS  1e-5f
#define DPROJP  1280         // DPROJ padded to 128
#define TCH     32           // conv time-chunk
#define PADR    8            // padded rows for clamp-free scan prefetch

// ---------------- scratch (device globals; allocation-free) ----------------
__device__ __half g_hh[NROWS*DMODEL];            // residual stream (fp16)
__device__ __half g_zxh[NROWS*DPROJ];            // zxbcdt (fp16)
__device__ __half g_xacth[(NROWS+PADR)*DINNER];  // silu(conv(x)) (fp16)
__device__ float  g_bcf[(NROWS+PADR)*2*DSTATE];  // conv'd B,C (fp32)
__device__ float2 g_dtA[(NROWS+PADR)*NHEADS];    // (softplus dt, exp(dt*A))
__device__ __half g_y0h[NROWS*DINNER];           // scan partial (n 0..31)
__device__ __half g_y1h[NROWS*DINNER];           // scan partial (n 32..63)
__device__ __half g_mh[NROWS*DMODEL];            // y @ W_out (fp16)

// fp16 activations (GEMM A operands)
__device__ __half g_xh[NROWS*NCH];
__device__ __half g_yh[NROWS*DINNER];

// fp16 transposed weights (GEMM B operands), [Npad][K]
__device__ __half g_linw[DMODEL*NCH];
__device__ __half g_winw[NLAYERS*DPROJP*DMODEL];
__device__ __half g_woutw[NLAYERS*DMODEL*DINNER];

__device__ __forceinline__ float siluf(float x) {
    return x * (1.f / (1.f + __expf(-x)));
}

__device__ __forceinline__ uint32_t smem_u32(const void* p) {
    uint32_t a;
    asm("{ .reg .u64 t; cvta.to.shared.u64 t, %1; cvt.u32.u64 %0, t; }"
        : "=r"(a) : "l"(p));
    return a;
}

#define LDM_X4(r0, r1, r2, r3, addr) \
    asm volatile("ldmatrix.sync.aligned.m8n8.x4.shared.b16 {%0,%1,%2,%3}, [%4];" \
        : "=r"(r0), "=r"(r1), "=r"(r2), "=r"(r3) : "r"(addr))

#define MMA_FP16(c, a, b0v, b1v) \
    asm volatile("mma.sync.aligned.m16n8k16.row.col.f32.f16.f16.f32 " \
        "{%0,%1,%2,%3}, {%4,%5,%6,%7}, {%8,%9}, {%0,%1,%2,%3};" \
        : "+f"((c)[0]), "+f"((c)[1]), "+f"((c)[2]), "+f"((c)[3]) \
        : "r"((a)[0]), "r"((a)[1]), "r"((a)[2]), "r"((a)[3]), \
          "r"(b0v), "r"(b1v))

#define CP16(dst, src) \
    asm volatile("cp.async.cg.shared.global [%0], [%1], 16;" \
        :: "r"(dst), "l"(src) : "memory")
#define CPCOMMIT() asm volatile("cp.async.commit_group;" ::: "memory")
#define CPWAIT(n)  asm volatile("cp.async.wait_group %0;" :: "n"(n) : "memory")

// ---------------- weight / input conversion ----------------
__global__ void k_cvt_w(const float* __restrict__ src, __half* __restrict__ dh,
                        int K, int N, int srcStrideLayer, int dstStrideLayer)
{
    int n = blockIdx.x;
    int l = blockIdx.y;
    int k = threadIdx.x;                 // blockDim.x == K
    float v = (n < N) ? src[(size_t)l*srcStrideLayer + (size_t)k*N + n] : 0.f;
    dh[(size_t)l*dstStrideLayer + (size_t)n*K + k] = __float2half_rn(v);
}

__global__ void k_cvt_x(const float* __restrict__ src, __half* __restrict__ d)
{
    int i = blockIdx.x * 256 + threadIdx.x;
    d[i] = __float2half_rn(src[i]);
}

// ============================================================================
// Single-pass fp16 tensor-core GEMM (proven 2-stage version)
// C[M,N] = A[M,K] @ B[K,N](stored [Npad][K]) (+bias), fp32 accumulate.
// CTA 128x128, BK=32, 8 warps (4m x 2n), 2-stage cp.async pipeline.
// ============================================================================
#define GSTRIDE 40
#define TILEB   (128*GSTRIDE*2)
#define STAGEB  (2*TILEB)
#define GT_SMEM (2*STAGEB)

__global__ __launch_bounds__(256, 2) void k_gemm_fp16(
    const __half* __restrict__ A, const __half* __restrict__ B,
    const float* __restrict__ bias, float* __restrict__ C,
    __half* __restrict__ Ch, int N, int K)
{
    extern __shared__ __align__(128) uint8_t dsm[];
    const uint32_t smb = smem_u32(dsm);

    int tid = threadIdx.x;
    int wid = tid >> 5, lane = tid & 31;
    int m0 = blockIdx.y * 128, n0 = blockIdx.x * 128;
    int wm = wid & 3, wn = wid >> 2;

    float acc[2][8][4];
#pragma unroll
    for (int mt = 0; mt < 2; mt++)
#pragma unroll
        for (int nt = 0; nt < 8; nt++)
#pragma unroll
            for (int j = 0; j < 4; j++) acc[mt][nt][j] = 0.f;

    const __half* srcs[2] = { A + (size_t)m0 * K, B + (size_t)n0 * K };
    const int row0 = tid >> 2, part = tid & 3;

    const uint32_t aoff = (uint32_t)((wm*32 + (lane & 7) + ((lane >> 3) & 1) * 8) * (GSTRIDE*2))
                        + ((lane >> 4) & 1) * 16;
    const uint32_t boff = (uint32_t)((wn*64 + (lane & 7) + ((lane >> 4) & 1) * 8) * (GSTRIDE*2))
                        + ((lane >> 3) & 1) * 16;

    const int NC = K >> 5;

#pragma unroll
    for (int t = 0; t < 2; t++) {
#pragma unroll
        for (int it = 0; it < 2; it++) {
            int r = row0 + it * 64;
            uint32_t d = smb + t * TILEB + (uint32_t)(r * (GSTRIDE*2) + part * 16);
            CP16(d, srcs[t] + (size_t)r * K + part * 8);
        }
    }
    CPCOMMIT();

    for (int c = 0; c < NC; c++) {
        int s = c & 1;
        if (c + 1 < NC) {
            uint32_t sb2 = smb + ((c + 1) & 1) * STAGEB;
            int kb = (c + 1) * 32;
#pragma unroll
            for (int t = 0; t < 2; t++) {
#pragma unroll
                for (int it = 0; it < 2; it++) {
                    int r = row0 + it * 64;
                    uint32_t d = sb2 + t * TILEB + (uint32_t)(r * (GSTRIDE*2) + part * 16);
                    CP16(d, srcs[t] + (size_t)r * K + kb + part * 8);
                }
            }
            CPCOMMIT();
            CPWAIT(1);
        } else {
            CPWAIT(0);
        }
        __syncthreads();

        uint32_t sbase = smb + s * STAGEB;
#pragma unroll
        for (int ks = 0; ks < 2; ks++) {
            uint32_t abase = sbase + aoff + ks * 32;
            uint32_t ra[2][4];
            LDM_X4(ra[0][0], ra[0][1], ra[0][2], ra[0][3], abase);
            LDM_X4(ra[1][0], ra[1][1], ra[1][2], ra[1][3],
                   abase + 16 * (GSTRIDE*2));
            uint32_t rb[8][2];
            uint32_t bbase = sbase + TILEB + boff + ks * 32;
#pragma unroll
            for (int g = 0; g < 4; g++)
                LDM_X4(rb[2*g][0], rb[2*g][1], rb[2*g+1][0], rb[2*g+1][1],
                       bbase + g * 16 * (GSTRIDE*2));
#pragma unroll
            for (int mt = 0; mt < 2; mt++)
#pragma unroll
                for (int nt = 0; nt < 8; nt++)
                    MMA_FP16(acc[mt][nt], ra[mt], rb[nt][0], rb[nt][1]);
        }
        __syncthreads();
    }

    const int gid = lane >> 2, tig = lane & 3;
#pragma unroll
    for (int mt = 0; mt < 2; mt++) {
#pragma unroll
        for (int nt = 0; nt < 8; nt++) {
            int col = n0 + wn * 64 + nt * 8 + tig * 2;
            if (col < N) {
                int r0 = m0 + wm * 32 + mt * 16 + gid;
                float2 v0 = make_float2(acc[mt][nt][0], acc[mt][nt][1]);
                float2 v1 = make_float2(acc[mt][nt][2], acc[mt][nt][3]);
                if (bias) {
                    float b0 = bias[col], b1 = bias[col + 1];
                    v0.x += b0; v0.y += b1; v1.x += b0; v1.y += b1;
                }
                if (C) {
                    *(float2*)(C + (size_t)r0 * N + col) = v0;
                    *(float2*)(C + (size_t)(r0 + 8) * N + col) = v1;
                }
                if (Ch) {
                    *(__half2*)(Ch + (size_t)r0 * N + col) =
                        __floats2half2_rn(v0.x, v0.y);
                    *(__half2*)(Ch + (size_t)(r0 + 8) * N + col) =
                        __floats2half2_rn(v1.x, v1.y);
                }
            }
        }
    }
}

// ------- causal depthwise conv(4) + SiLU + dt/dA, half2 vectorized -------
// 320 threads, each handles channels (2ci, 2ci+1). Tap history in registers.
#define CONVT 320
__global__ __launch_bounds__(CONVT) void k_conv_dt(
    const float* __restrict__ conv_w, const float* __restrict__ conv_b,
    const float* __restrict__ dt_bias, const float* __restrict__ A_log,
    int layer)
{
    int t0 = blockIdx.x * TCH;
    int b  = blockIdx.y;
    int ci = threadIdx.x;                 // 0..319
    int c0 = ci * 2;                      // channel pair (c0, c0+1)

    const float4* wr4 = (const float4*)(conv_w + ((size_t)layer*CONVDIM + c0)*4);
    float4 wA = wr4[0], wB = wr4[1];
    float2 cb = *(const float2*)(conv_b + layer*CONVDIM + c0);

    const __half2* zc = (const __half2*)(g_zxh + (size_t)(b*SEQ)*DPROJ + DINNER + c0);
    float2 h3 = make_float2(0.f, 0.f), h2 = h3, h1 = h3;
    if (t0 >= 3) {
        h3 = __half22float2(zc[(size_t)(t0-3)*(DPROJ/2)]);
        h2 = __half22float2(zc[(size_t)(t0-2)*(DPROJ/2)]);
        h1 = __half22float2(zc[(size_t)(t0-1)*(DPROJ/2)]);
    }

    // dt path: thread ci<4 handles heads c0, c0+1
    float2 dtb = make_float2(0.f, 0.f), Aneg = dtb;
    const __half2* dz = nullptr;
    if (ci < 4) {
        dtb  = make_float2(dt_bias[layer*NHEADS + c0], dt_bias[layer*NHEADS + c0 + 1]);
        Aneg = make_float2(-expf(A_log[layer*NHEADS + c0]),
                           -expf(A_log[layer*NHEADS + c0 + 1]));
        dz = (const __half2*)(g_zxh + (size_t)(b*SEQ)*DPROJ + DINNER + CONVDIM + c0);
    }

    bool isx = (c0 < DINNER);
    __half2* xo = (__half2*)(g_xacth + (size_t)(b*SEQ + t0)*DINNER + c0);
    float2*  bo = (float2*)(g_bcf + (size_t)(b*SEQ + t0)*(2*DSTATE) + (c0 - DINNER));

#pragma unroll 4
    for (int u = 0; u < TCH; u++) {
        float2 cur = __half22float2(zc[(size_t)(t0+u)*(DPROJ/2)]);
        float sx_ = cb.x + h3.x*wA.x + h2.x*wA.y + h1.x*wA.z + cur.x*wA.w;
        float sy_ = cb.y + h3.y*wB.x + h2.y*wB.y + h1.y*wB.z + cur.y*wB.w;
        float ax = siluf(sx_), ay = siluf(sy_);
        if (isx) xo[(size_t)u*(DINNER/2)] = __floats2half2_rn(ax, ay);
        else     bo[(size_t)u*DSTATE]     = make_float2(ax, ay);
        h3 = h2; h2 = h1; h1 = cur;
        if (ci < 4) {
            float2 dr = __half22float2(dz[(size_t)(t0+u)*(DPROJ/2)]);
            float d0 = dr.x + dtb.x, d1 = dr.y + dtb.y;
            float dt0 = (d0 > 20.f) ? d0 : log1pf(expf(d0));
            float dt1 = (d1 > 20.f) ? d1 : log1pf(expf(d1));
            float4 v = make_float4(dt0, expf(dt0*Aneg.x), dt1, expf(dt1*Aneg.y));
            *(float4*)(&g_dtA[(size_t)(b*SEQ + t0 + u)*NHEADS + c0]) = v;
        }
    }
}

// ---------------- sequential selective scan (half-split, clamp-free) ---------
__global__ __launch_bounds__(256) void k_scan(
    const float* __restrict__ Dp, int layer)
{
    int bh = blockIdx.x >> 1, half = blockIdx.x & 1;
    int b = bh >> 3, h = bh & 7;
    int tid = threadIdx.x;
    int p = tid >> 2, q = tid & 3;
    int n0 = half*32 + q*8;

    float S[8];
#pragma unroll
    for (int j = 0; j < 8; j++) S[j] = 0.f;

    float Dh = (half == 0) ? Dp[layer*NHEADS + h] : 0.f;

    const __half*  xrow = g_xacth + (size_t)(b*SEQ)*DINNER + h*HP + p;
    const float2*  dap  = g_dtA   + (size_t)(b*SEQ)*NHEADS + h;
    const float*   bcb  = g_bcf   + (size_t)(b*SEQ)*(2*DSTATE) + n0;
    __half* yp = (half == 0 ? g_y0h : g_y1h)
               + (size_t)(b*SEQ)*DINNER + h*HP + p;

    float sx[4]; float2 sda[4];
    float sB[4][8], sC[4][8];
#pragma unroll
    for (int u = 0; u < 4; u++) {
        sx[u]  = __half2float(xrow[(size_t)u*DINNER]);
        sda[u] = dap[u*NHEADS];
        const float* bc = bcb + (size_t)u*(2*DSTATE);
        ((float4*)sB[u])[0] = *(const float4*)(bc);
        ((float4*)sB[u])[1] = *(const float4*)(bc + 4);
        ((float4*)sC[u])[0] = *(const float4*)(bc + DSTATE);
        ((float4*)sC[u])[1] = *(const float4*)(bc + DSTATE + 4);
    }

    // running prefetch pointers (start at t=4); padded arrays make the
    // final out-of-range prefetches safe (values never consumed).
    const __half*  px  = xrow + 4*DINNER;
    const float2*  pd  = dap  + 4*NHEADS;
    const float*   pbc = bcb  + 4*(2*DSTATE);

    for (int t = 0; t < SEQ; t += 4) {
#pragma unroll
        for (int u = 0; u < 4; u++) {
            float xv = sx[u];
            float2 da = sda[u];
            float coef = da.x * xv;
            float a0 = 0.f, a1 = 0.f;
#pragma unroll
            for (int j = 0; j < 4; j++) {
                S[j] = S[j]*da.y + coef*sB[u][j];
                a0 += S[j]*sC[u][j];
            }
#pragma unroll
            for (int j = 4; j < 8; j++) {
                S[j] = S[j]*da.y + coef*sB[u][j];
                a1 += S[j]*sC[u][j];
            }
            float acc = a0 + a1;
            acc += __shfl_xor_sync(0xffffffffu, acc, 1);
            acc += __shfl_xor_sync(0xffffffffu, acc, 2);
            if (q == 0)
                yp[(size_t)(t+u)*DINNER] = __float2half_rn(acc + Dh*xv);

            // prefetch slot u for step t+u+4 (constant offsets from bases)
            sx[u]  = __half2float(px[(size_t)u*DINNER]);
            sda[u] = pd[u*NHEADS];
            const float* bc = pbc + (size_t)u*(2*DSTATE);
            ((float4*)sB[u])[0] = *(const float4*)(bc);
            ((float4*)sB[u])[1] = *(const float4*)(bc + 4);
            ((float4*)sC[u])[0] = *(const float4*)(bc + DSTATE);
            ((float4*)sC[u])[1] = *(const float4*)(bc + DSTATE + 4);
        }
        px  += 4*DINNER;
        pd  += 4*NHEADS;
        pbc += 4*(2*DSTATE);
    }
}

// ---------------- gated RMSNorm: y = rmsnorm((y0+y1) * silu(z)) -> fp16 ----------------
__global__ __launch_bounds__(256) void k_gate_rms(
    const float* __restrict__ norm_w, int layer)
{
    int row = blockIdx.x;
    int tid = threadIdx.x;
    int lane = tid & 31, wid = tid >> 5;
    __shared__ float red[8];

    const __half* zrow = g_zxh + (size_t)row*DPROJ;
    size_t base = (size_t)row*DINNER;

    float y0a = __half2float(g_y0h[base + tid])       + __half2float(g_y1h[base + tid]);
    float y1a = __half2float(g_y0h[base + tid + 256]) + __half2float(g_y1h[base + tid + 256]);
    float v0 = y0a * siluf(__half2float(zrow[tid]));
    float v1 = y1a * siluf(__half2float(zrow[tid + 256]));
    float s = v0*v0 + v1*v1;
#pragma unroll
    for (int o = 16; o > 0; o >>= 1) s += __shfl_xor_sync(0xffffffffu, s, o);
    if (lane == 0) red[wid] = s;
    __syncthreads();
    if (tid < 32) {
        float v = (lane < 8) ? red[lane] : 0.f;
#pragma unroll
        for (int o = 4; o > 0; o >>= 1) v += __shfl_xor_sync(0xffffffffu, v, o);
        if (lane == 0) red[0] = v;
    }
    __syncthreads();
    float scale = rsqrtf(red[0] * (1.f/DINNER) + LN_EPS);
    g_yh[base + tid]       = __float2half_rn(v0 * scale * norm_w[layer*DINNER + tid]);
    g_yh[base + tid + 256] = __float2half_rn(v1 * scale * norm_w[layer*DINNER + tid + 256]);
}

// ------- residual + LayerNorm: h = LN(m + h), fp16 residual stream -------
__global__ __launch_bounds__(256) void k_res_ln(
    const float* __restrict__ ln_w, const float* __restrict__ ln_b, int layer)
{
    int row = blockIdx.x;
    int tid = threadIdx.x;
    int lane = tid & 31, wid = tid >> 5;
    __shared__ float red1[8], red2[8];

    size_t o = (size_t)row*DMODEL + tid;
    float u = __half2float(g_mh[o]) + __half2float(g_hh[o]);
    float s1 = u, s2 = u*u;
#pragma unroll
    for (int ofs = 16; ofs > 0; ofs >>= 1) {
        s1 += __shfl_xor_sync(0xffffffffu, s1, ofs);
        s2 += __shfl_xor_sync(0xffffffffu, s2, ofs);
    }
    if (lane == 0) { red1[wid] = s1; red2[wid] = s2; }
    __syncthreads();
    if (tid < 32) {
        float a = (lane < 8) ? red1[lane] : 0.f;
        float c = (lane < 8) ? red2[lane] : 0.f;
#pragma unroll
        for (int ofs = 4; ofs > 0; ofs >>= 1) {
            a += __shfl_xor_sync(0xffffffffu, a, ofs);
            c += __shfl_xor_sync(0xffffffffu, c, ofs);
        }
        if (lane == 0) { red1[0] = a; red2[0] = c; }
    }
    __syncthreads();
    float mu  = red1[0] * (1.f/DMODEL);
    float var = red2[0] * (1.f/DMODEL) - mu*mu;
    float outv = (u - mu) * rsqrtf(var + LN_EPS) * ln_w[layer*DMODEL + tid]
               + ln_b[layer*DMODEL + tid];
    g_hh[o] = __float2half_rn(outv);
}

// ---- final layer: residual + LayerNorm + linear_out fused -> d_out ----
__global__ __launch_bounds__(256) void k_res_ln_out(
    const float* __restrict__ ln_w, const float* __restrict__ ln_b, int layer,
    const float* __restrict__ w, const float* __restrict__ bias,
    float* __restrict__ out)
{
    int row = blockIdx.x;
    int tid = threadIdx.x;
    int lane = tid & 31, wid = tid >> 5;
    __shared__ float red1[8], red2[8];
    __shared__ float red5[8][5];

    size_t o = (size_t)row*DMODEL + tid;
    float u = __half2float(g_mh[o]) + __half2float(g_hh[o]);
    float s1 = u, s2 = u*u;
#pragma unroll
    for (int ofs = 16; ofs > 0; ofs >>= 1) {
        s1 += __shfl_xor_sync(0xffffffffu, s1, ofs);
        s2 += __shfl_xor_sync(0xffffffffu, s2, ofs);
    }
    if (lane == 0) { red1[wid] = s1; red2[wid] = s2; }
    __syncthreads();
    if (tid < 32) {
        float a = (lane < 8) ? red1[lane] : 0.f;
        float c = (lane < 8) ? red2[lane] : 0.f;
#pragma unroll
        for (int ofs = 4; ofs > 0; ofs >>= 1) {
            a += __shfl_xor_sync(0xffffffffu, a, ofs);
            c += __shfl_xor_sync(0xffffffffu, c, ofs);
        }
        if (lane == 0) { red1[0] = a; red2[0] = c; }
    }
    __syncthreads();
    float mu  = red1[0] * (1.f/DMODEL);
    float var = red2[0] * (1.f/DMODEL) - mu*mu;
    float outv = (u - mu) * rsqrtf(var + LN_EPS) * ln_w[layer*DMODEL + tid]
               + ln_b[layer*DMODEL + tid];

    float a0 = outv * w[tid*5 + 0];
    float a1 = outv * w[tid*5 + 1];
    float a2 = outv * w[tid*5 + 2];
    float a3 = outv * w[tid*5 + 3];
    float a4 = outv * w[tid*5 + 4];
#pragma unroll
    for (int ofs = 16; ofs > 0; ofs >>= 1) {
        a0 += __shfl_xor_sync(0xffffffffu, a0, ofs);
        a1 += __shfl_xor_sync(0xffffffffu, a1, ofs);
        a2 += __shfl_xor_sync(0xffffffffu, a2, ofs);
        a3 += __shfl_xor_sync(0xffffffffu, a3, ofs);
        a4 += __shfl_xor_sync(0xffffffffu, a4, ofs);
    }
    if (lane == 0) {
        red5[wid][0] = a0; red5[wid][1] = a1; red5[wid][2] = a2;
        red5[wid][3] = a3; red5[wid][4] = a4;
    }
    __syncthreads();
    if (tid < 5) {
        float s = 0.f;
#pragma unroll
        for (int j = 0; j < 8; j++) s += red5[j][tid];
        out[(size_t)row*5 + tid] = s + bias[tid];
    }
}

// ---------------- launcher ----------------
extern "C" void kernel_launch(void* const* d_in, const int* in_sizes, int n_in,
                              void* d_out, int out_size)
{
    const float* x         = (const float*)d_in[0];
    const float* lin_in_w  = (const float*)d_in[1];
    const float* lin_in_b  = (const float*)d_in[2];
    const float* W_in      = (const float*)d_in[3];
    const float* conv_w    = (const float*)d_in[4];
    const float* conv_b    = (const float*)d_in[5];
    const float* dt_bias   = (const float*)d_in[6];
    const float* A_log     = (const float*)d_in[7];
    const float* Dp        = (const float*)d_in[8];
    const float* norm_w    = (const float*)d_in[9];
    const float* W_out     = (const float*)d_in[10];
    const float* ln_w      = (const float*)d_in[11];
    const float* ln_b      = (const float*)d_in[12];
    const float* lin_out_w = (const float*)d_in[13];
    const float* lin_out_b = (const float*)d_in[14];
    float* out = (float*)d_out;

    void *phh, *pzxh, *pmh, *pxh, *pyh;
    cudaGetSymbolAddress(&phh, g_hh);
    cudaGetSymbolAddress(&pzxh, g_zxh);
    cudaGetSymbolAddress(&pmh, g_mh);
    cudaGetSymbolAddress(&pxh, g_xh);
    cudaGetSymbolAddress(&pyh, g_yh);
    void *plw, *pwiw, *pwow;
    cudaGetSymbolAddress(&plw, g_linw);
    cudaGetSymbolAddress(&pwiw, g_winw);
    cudaGetSymbolAddress(&pwow, g_woutw);

    static bool attrset = false;
    if (!attrset) {
        cudaFuncSetAttribute(k_gemm_fp16,
            cudaFuncAttributeMaxDynamicSharedMemorySize, GT_SMEM);
        attrset = true;
    }

    // ---- conversions + linear_in (launch index 3 = GEMM for ncu) ----
    k_cvt_x<<<NROWS*NCH/256, 256>>>(x, (__half*)pxh);
    k_cvt_w<<<dim3(DMODEL, 1), NCH>>>(lin_in_w, (__half*)plw,
        NCH, DMODEL, 0, 0);
    k_cvt_w<<<dim3(DPROJP, NLAYERS), DMODEL>>>(W_in, (__half*)pwiw,
        DMODEL, DPROJ, DMODEL*DPROJ, DPROJP*DMODEL);
    k_gemm_fp16<<<dim3(2, NROWS/128), 256, GT_SMEM>>>(
        (const __half*)pxh, (const __half*)plw,
        lin_in_b, nullptr, (__half*)phh, DMODEL, NCH);
    k_cvt_w<<<dim3(DMODEL, NLAYERS), DINNER>>>(W_out, (__half*)pwow,
        DINNER, DMODEL, DINNER*DMODEL, DMODEL*DINNER);

    for (int l = 0; l < NLAYERS; l++) {
        // zxbcdt (fp16 only)
        k_gemm_fp16<<<dim3(DPROJP/128, NROWS/128), 256, GT_SMEM>>>(
            (const __half*)phh,
            (const __half*)pwiw + (size_t)l*DPROJP*DMODEL,
            nullptr, nullptr, (__half*)pzxh, DPROJ, DMODEL);

        k_conv_dt<<<dim3(SEQ/TCH, BATCH), CONVT>>>(conv_w, conv_b, dt_bias, A_log, l);

        k_scan<<<BATCH*NHEADS*2, 256>>>(Dp, l);

        k_gate_rms<<<NROWS, 256>>>(norm_w, l);

        // m = y @ W_out (fp16 only)
        k_gemm_fp16<<<dim3(DMODEL/128, NROWS/128), 256, GT_SMEM>>>(
            (const __half*)pyh,
            (const __half*)pwow + (size_t)l*DMODEL*DINNER,
            nullptr, nullptr, (__half*)pmh, DMODEL, DINNER);

        if (l < NLAYERS - 1)
            k_res_ln<<<NROWS, 256>>>(ln_w, ln_b, l);
        else
            k_res_ln_out<<<NROWS, 256>>>(ln_w, ln_b, l,
                                         lin_out_w, lin_out_b, out);
    }
}